// round 1
// baseline (speedup 1.0000x reference)
#include <cuda_runtime.h>
#include <math.h>
#include <stdint.h>

#define BATCH  2
#define SEQ    2048
#define DMODEL 1024
#define NHEAD  16
#define DHEAD  64
#define MROWS  (BATCH*SEQ)   // 4096

// Scratch (allocation-free rule: __device__ globals)
__device__ float g_Q[MROWS*DMODEL];
__device__ float g_K[MROWS*DMODEL];
__device__ float g_V[MROWS*DMODEL];
__device__ float g_C[MROWS*DMODEL];

// ---------------------------------------------------------------------------
// Y[M,N] = X[M,K] @ W[N,K]^T + bias   (torch Linear). M%128==0, N%128==0, K%8==0.
// 128x128 block tile, BK=8, 256 threads, 8x8 per thread.
// ---------------------------------------------------------------------------
__global__ __launch_bounds__(256, 2)
void sgemm_nt_bias(const float* __restrict__ X, const float* __restrict__ W,
                   const float* __restrict__ bias, float* __restrict__ Y,
                   int M, int N, int K)
{
    __shared__ float As[8 * 128];
    __shared__ float Bs[8 * 128];

    const int tid = threadIdx.x;
    const int tx  = tid & 15;        // 0..15 (N sub-tiles)
    const int ty  = tid >> 4;        // 0..15 (M sub-tiles)
    const int row0 = blockIdx.y * 128;
    const int col0 = blockIdx.x * 128;

    // cooperative load mapping: each thread loads one float4 of X and one of W
    const int lr = tid >> 1;         // 0..127 row within tile
    const int lc = (tid & 1) * 4;    // 0 or 4 (column group within BK=8)

    const float* Xp = X + (size_t)(row0 + lr) * K + lc;
    const float* Wp = W + (size_t)(col0 + lr) * K + lc;

    float acc[8][8];
#pragma unroll
    for (int i = 0; i < 8; ++i)
#pragma unroll
        for (int j = 0; j < 8; ++j) acc[i][j] = 0.f;

    for (int k0 = 0; k0 < K; k0 += 8) {
        float4 xa = *(const float4*)(Xp + k0);
        float4 wb = *(const float4*)(Wp + k0);
        As[(lc + 0) * 128 + lr] = xa.x;
        As[(lc + 1) * 128 + lr] = xa.y;
        As[(lc + 2) * 128 + lr] = xa.z;
        As[(lc + 3) * 128 + lr] = xa.w;
        Bs[(lc + 0) * 128 + lr] = wb.x;
        Bs[(lc + 1) * 128 + lr] = wb.y;
        Bs[(lc + 2) * 128 + lr] = wb.z;
        Bs[(lc + 3) * 128 + lr] = wb.w;
        __syncthreads();

#pragma unroll
        for (int kk = 0; kk < 8; ++kk) {
            float a[8], b[8];
            *(float4*)(a)     = *(const float4*)&As[kk * 128 + ty * 8];
            *(float4*)(a + 4) = *(const float4*)&As[kk * 128 + ty * 8 + 4];
            *(float4*)(b)     = *(const float4*)&Bs[kk * 128 + tx * 8];
            *(float4*)(b + 4) = *(const float4*)&Bs[kk * 128 + tx * 8 + 4];
#pragma unroll
            for (int i = 0; i < 8; ++i)
#pragma unroll
                for (int j = 0; j < 8; ++j)
                    acc[i][j] = fmaf(a[i], b[j], acc[i][j]);
        }
        __syncthreads();
    }

    // epilogue with bias, vectorized stores
#pragma unroll
    for (int i = 0; i < 8; ++i) {
        const int row = row0 + ty * 8 + i;
        float* yp = Y + (size_t)row * N + col0 + tx * 8;
#pragma unroll
        for (int j0 = 0; j0 < 8; j0 += 4) {
            float4 o;
            o.x = acc[i][j0 + 0] + bias[col0 + tx * 8 + j0 + 0];
            o.y = acc[i][j0 + 1] + bias[col0 + tx * 8 + j0 + 1];
            o.z = acc[i][j0 + 2] + bias[col0 + tx * 8 + j0 + 2];
            o.w = acc[i][j0 + 3] + bias[col0 + tx * 8 + j0 + 3];
            *(float4*)(yp + j0) = o;
        }
    }
}

// ---------------------------------------------------------------------------
// Flash attention, fp32, no score materialization.
// Q/K/V stored [B,S,D], head h = columns [h*64, h*64+64).
// Block = (q-tile of 64 rows) x (one b,h). 256 threads, 16x16 grid, 4x4/thread.
// Online softmax with per-row m,l. Mask [1,1,S,S] applied faithfully.
// ---------------------------------------------------------------------------
#define QT 64
#define KT 64
// shared layout strides
#define QS_STR 65
#define KS_STR 65
#define PS_STR 65
#define VS_STR 68   // multiple of 4 -> aligned float4 rows
#define SMEM_FLOATS (64*QS_STR + 64*KS_STR + 64*PS_STR + 64*VS_STR)

__global__ __launch_bounds__(256)
void flash_attn(const float* __restrict__ Qb, const float* __restrict__ Kb,
                const float* __restrict__ Vb, const int* __restrict__ mask,
                float* __restrict__ Cb)
{
    extern __shared__ float sm[];
    float* Qs = sm;                    // [64][65]
    float* Ks = Qs + 64 * QS_STR;      // [64][65]
    float* Ps = Ks + 64 * KS_STR;      // [64][65]
    float* Vs = Ps + 64 * PS_STR;      // [64][68]

    const int tid = threadIdx.x;
    const int tx = tid & 15;           // 0..15 -> 4 cols each
    const int ty = tid >> 4;           // 0..15 -> 4 rows each
    const int bh = blockIdx.y;         // 0..31
    const int b  = bh >> 4;
    const int h  = bh & 15;
    const int q0 = blockIdx.x * QT;

    const float* Qptr = Qb + ((size_t)(b * SEQ + q0)) * DMODEL + h * DHEAD;

    // load Q tile (64x64) -> Qs
    for (int i = tid; i < 64 * 16; i += 256) {
        const int r  = i >> 4;
        const int c4 = (i & 15) * 4;
        float4 v = *(const float4*)(Qptr + (size_t)r * DMODEL + c4);
        float* dst = &Qs[r * QS_STR + c4];
        dst[0] = v.x; dst[1] = v.y; dst[2] = v.z; dst[3] = v.w;
    }

    float mrow[4], lrow[4], acc[4][4];
#pragma unroll
    for (int i = 0; i < 4; ++i) {
        mrow[i] = -INFINITY; lrow[i] = 0.f;
#pragma unroll
        for (int j = 0; j < 4; ++j) acc[i][j] = 0.f;
    }
    __syncthreads();

    for (int kt = 0; kt < SEQ / KT; ++kt) {
        const int k0 = kt * KT;
        const float* Kptr = Kb + ((size_t)(b * SEQ + k0)) * DMODEL + h * DHEAD;
        const float* Vptr = Vb + ((size_t)(b * SEQ + k0)) * DMODEL + h * DHEAD;

        // load K,V tiles
        for (int i = tid; i < 64 * 16; i += 256) {
            const int r  = i >> 4;
            const int c4 = (i & 15) * 4;
            float4 kv = *(const float4*)(Kptr + (size_t)r * DMODEL + c4);
            float* kd = &Ks[r * KS_STR + c4];
            kd[0] = kv.x; kd[1] = kv.y; kd[2] = kv.z; kd[3] = kv.w;
            float4 vv = *(const float4*)(Vptr + (size_t)r * DMODEL + c4);
            float* vd = &Vs[r * VS_STR + c4];
            vd[0] = vv.x; vd[1] = vv.y; vd[2] = vv.z; vd[3] = vv.w;
        }
        __syncthreads();

        // S = Q K^T  (4x4 per thread)
        float s[4][4];
#pragma unroll
        for (int i = 0; i < 4; ++i)
#pragma unroll
            for (int j = 0; j < 4; ++j) s[i][j] = 0.f;

#pragma unroll 4
        for (int d = 0; d < DHEAD; ++d) {
            float qv[4], kv[4];
#pragma unroll
            for (int i = 0; i < 4; ++i) qv[i] = Qs[(ty * 4 + i) * QS_STR + d];
#pragma unroll
            for (int j = 0; j < 4; ++j) kv[j] = Ks[(tx * 4 + j) * KS_STR + d];
#pragma unroll
            for (int i = 0; i < 4; ++i)
#pragma unroll
                for (int j = 0; j < 4; ++j)
                    s[i][j] = fmaf(qv[i], kv[j], s[i][j]);
        }

        // scale + mask
#pragma unroll
        for (int i = 0; i < 4; ++i) {
            const int qrow = q0 + ty * 4 + i;
#pragma unroll
            for (int j = 0; j < 4; ++j) {
                const int kcol = k0 + tx * 4 + j;
                const int mv = mask[(size_t)qrow * SEQ + kcol];
                s[i][j] = (mv != 0) ? s[i][j] * 0.125f : -1e9f;
            }
        }

        // row max (reduce across tx: 16 lanes within half-warp)
        float rmax[4];
#pragma unroll
        for (int i = 0; i < 4; ++i) {
            float v = fmaxf(fmaxf(s[i][0], s[i][1]), fmaxf(s[i][2], s[i][3]));
#pragma unroll
            for (int off = 8; off > 0; off >>= 1)
                v = fmaxf(v, __shfl_xor_sync(0xffffffffu, v, off, 16));
            rmax[i] = v;
        }

        float scale[4];
#pragma unroll
        for (int i = 0; i < 4; ++i) {
            const float mnew = fmaxf(mrow[i], rmax[i]);
            scale[i] = __expf(mrow[i] - mnew);
            mrow[i]  = mnew;
        }

        // P = exp(s - m), row sums
        float rsum[4];
#pragma unroll
        for (int i = 0; i < 4; ++i) {
            float sum = 0.f;
#pragma unroll
            for (int j = 0; j < 4; ++j) {
                const float p = __expf(s[i][j] - mrow[i]);
                s[i][j] = p;
                sum += p;
            }
#pragma unroll
            for (int off = 8; off > 0; off >>= 1)
                sum += __shfl_xor_sync(0xffffffffu, sum, off, 16);
            rsum[i] = sum;
        }

#pragma unroll
        for (int i = 0; i < 4; ++i) {
            lrow[i] = lrow[i] * scale[i] + rsum[i];
#pragma unroll
            for (int j = 0; j < 4; ++j) acc[i][j] *= scale[i];
        }

        // stage P to shared for the PV product
#pragma unroll
        for (int i = 0; i < 4; ++i)
#pragma unroll
            for (int j = 0; j < 4; ++j)
                Ps[(ty * 4 + i) * PS_STR + tx * 4 + j] = s[i][j];
        __syncthreads();

        // acc += P @ V
#pragma unroll 4
        for (int k = 0; k < KT; ++k) {
            float pv[4];
#pragma unroll
            for (int i = 0; i < 4; ++i) pv[i] = Ps[(ty * 4 + i) * PS_STR + k];
            float4 vv = *(const float4*)&Vs[k * VS_STR + tx * 4];
            const float vj[4] = {vv.x, vv.y, vv.z, vv.w};
#pragma unroll
            for (int i = 0; i < 4; ++i)
#pragma unroll
                for (int j = 0; j < 4; ++j)
                    acc[i][j] = fmaf(pv[i], vj[j], acc[i][j]);
        }
        __syncthreads();   // before K/V/P overwrite next iter
    }

    // epilogue: normalize and write context [B,S,D] (head cols h*64..)
#pragma unroll
    for (int i = 0; i < 4; ++i) {
        const float inv = 1.0f / lrow[i];
        const int row = b * SEQ + q0 + ty * 4 + i;
        float4 o;
        o.x = acc[i][0] * inv;
        o.y = acc[i][1] * inv;
        o.z = acc[i][2] * inv;
        o.w = acc[i][3] * inv;
        *(float4*)(Cb + (size_t)row * DMODEL + h * DHEAD + tx * 4) = o;
    }
}

// ---------------------------------------------------------------------------
extern "C" void kernel_launch(void* const* d_in, const int* in_sizes, int n_in,
                              void* d_out, int out_size)
{
    const float* q    = (const float*)d_in[0];
    const float* k    = (const float*)d_in[1];
    const float* v    = (const float*)d_in[2];
    const int*   mask = (const int*)  d_in[3];
    const float* Wq   = (const float*)d_in[4];
    const float* bq   = (const float*)d_in[5];
    const float* Wk   = (const float*)d_in[6];
    const float* bk   = (const float*)d_in[7];
    const float* Wv   = (const float*)d_in[8];
    const float* bv   = (const float*)d_in[9];
    const float* Wo   = (const float*)d_in[10];
    const float* bo   = (const float*)d_in[11];
    float* out = (float*)d_out;

    float *Qb, *Kb, *Vb, *Cb;
    cudaGetSymbolAddress((void**)&Qb, g_Q);
    cudaGetSymbolAddress((void**)&Kb, g_K);
    cudaGetSymbolAddress((void**)&Vb, g_V);
    cudaGetSymbolAddress((void**)&Cb, g_C);

    const dim3 gemmGrid(DMODEL / 128, MROWS / 128);  // (8, 32)
    sgemm_nt_bias<<<gemmGrid, 256>>>(q, Wq, bq, Qb, MROWS, DMODEL, DMODEL);
    sgemm_nt_bias<<<gemmGrid, 256>>>(k, Wk, bk, Kb, MROWS, DMODEL, DMODEL);
    sgemm_nt_bias<<<gemmGrid, 256>>>(v, Wv, bv, Vb, MROWS, DMODEL, DMODEL);

    static const size_t smemBytes = SMEM_FLOATS * sizeof(float);
    cudaFuncSetAttribute(flash_attn, cudaFuncAttributeMaxDynamicSharedMemorySize,
                         (int)smemBytes);
    flash_attn<<<dim3(SEQ / QT, BATCH * NHEAD), 256, smemBytes>>>(Qb, Kb, Vb, mask, Cb);

    sgemm_nt_bias<<<gemmGrid, 256>>>(Cb, Wo, bo, out, MROWS, DMODEL, DMODEL);
}

// round 4
// speedup vs baseline: 1.3232x; 1.3232x over previous
#include <cuda_runtime.h>
#include <cuda_bf16.h>
#include <math.h>
#include <stdint.h>

#define BATCH  2
#define SEQ    2048
#define DMODEL 1024
#define NHEAD  16
#define DHEAD  64
#define MROWS  (BATCH*SEQ)   // 4096
#define KSPLIT 3072          // [hi | lo | hi] along K

// ---------------------------------------------------------------------------
// Scratch (__device__ globals; no allocation allowed)
// ---------------------------------------------------------------------------
__device__ float g_Q[MROWS*DMODEL];
__device__ float g_K[MROWS*DMODEL];
__device__ float g_V[MROWS*DMODEL];
__device__ float g_C[MROWS*DMODEL];
__device__ __nv_bfloat16 g_Xs[MROWS*KSPLIT];    // A'' = [hi | lo | hi]
__device__ __nv_bfloat16 g_Ws[DMODEL*KSPLIT];   // B'' = [hi | hi | lo]

__device__ __forceinline__ uint32_t smem_u32(const void* p) {
    uint32_t a;
    asm("{ .reg .u64 t; cvta.to.shared.u64 t, %1; cvt.u32.u64 %0, t; }" : "=r"(a) : "l"(p));
    return a;
}

// ---------------------------------------------------------------------------
// fp32 -> split-bf16 expansion.
// X path: dst[row][0:1024]=hi, [1024:2048]=lo, [2048:3072]=hi
// W path: dst[row][0:1024]=hi, [1024:2048]=hi, [2048:3072]=lo
// ---------------------------------------------------------------------------
template<int LO_AT_MID>
__global__ void split3(const float* __restrict__ src,
                       __nv_bfloat16* __restrict__ dst, int n4)
{
    int i = blockIdx.x * blockDim.x + threadIdx.x;
    if (i >= n4) return;
    const int row = i >> 8;             // 1024 cols = 256 float4
    const int col = (i & 255) * 4;
    float4 x = ((const float4*)src)[i];
    __nv_bfloat16 h0 = __float2bfloat16_rn(x.x);
    __nv_bfloat16 h1 = __float2bfloat16_rn(x.y);
    __nv_bfloat16 h2 = __float2bfloat16_rn(x.z);
    __nv_bfloat16 h3 = __float2bfloat16_rn(x.w);
    __nv_bfloat16 l0 = __float2bfloat16_rn(x.x - __bfloat162float(h0));
    __nv_bfloat16 l1 = __float2bfloat16_rn(x.y - __bfloat162float(h1));
    __nv_bfloat16 l2 = __float2bfloat16_rn(x.z - __bfloat162float(h2));
    __nv_bfloat16 l3 = __float2bfloat16_rn(x.w - __bfloat162float(h3));
    __nv_bfloat162 hp0 = __halves2bfloat162(h0, h1);
    __nv_bfloat162 hp1 = __halves2bfloat162(h2, h3);
    __nv_bfloat162 lp0 = __halves2bfloat162(l0, l1);
    __nv_bfloat162 lp1 = __halves2bfloat162(l2, l3);
    uint2 hp = make_uint2(*(uint32_t*)&hp0, *(uint32_t*)&hp1);
    uint2 lp = make_uint2(*(uint32_t*)&lp0, *(uint32_t*)&lp1);
    __nv_bfloat16* base = dst + (size_t)row * KSPLIT + col;
    *(uint2*)(base)        = hp;
    *(uint2*)(base + 1024) = LO_AT_MID ? lp : hp;
    *(uint2*)(base + 2048) = LO_AT_MID ? hp : lp;
}

// ---------------------------------------------------------------------------
// bf16 mma.sync GEMM: Y[M,1024] = A''[M,3072] @ (B''[1024,3072])^T + bias
// CTA 128x128, K-step 32, 4-stage cp.async pipeline, 8 warps (32x64 warptile).
// ---------------------------------------------------------------------------
#define CTA_M   128
#define CTA_N   128
#define CTA_K   32
#define STAGES  4
#define ASTRIDE 40                         // bf16 elems per smem row (pad 8)
#define TILE_ELE  (128 * ASTRIDE)          // per operand per stage
#define STAGE_ELE (2 * TILE_ELE)
#define GEMM_SMEM (STAGES * STAGE_ELE * 2) // bytes = 81920

__device__ __forceinline__ void cp16(uint32_t smem, const void* gmem) {
    asm volatile("cp.async.cg.shared.global [%0], [%1], 16;" :: "r"(smem), "l"(gmem));
}
__device__ __forceinline__ void cp_commit() { asm volatile("cp.async.commit_group;"); }
template<int N> __device__ __forceinline__ void cp_wait() {
    asm volatile("cp.async.wait_group %0;" :: "n"(N));
}
__device__ __forceinline__ void ldsm4(uint32_t* r, uint32_t addr) {
    asm volatile("ldmatrix.sync.aligned.m8n8.x4.shared.b16 {%0,%1,%2,%3}, [%4];"
        : "=r"(r[0]), "=r"(r[1]), "=r"(r[2]), "=r"(r[3]) : "r"(addr));
}
__device__ __forceinline__ void mma16816(float* d, const uint32_t* a, const uint32_t* b) {
    asm volatile(
        "mma.sync.aligned.m16n8k16.row.col.f32.bf16.bf16.f32 "
        "{%0,%1,%2,%3}, {%4,%5,%6,%7}, {%8,%9}, {%0,%1,%2,%3};"
        : "+f"(d[0]), "+f"(d[1]), "+f"(d[2]), "+f"(d[3])
        : "r"(a[0]), "r"(a[1]), "r"(a[2]), "r"(a[3]), "r"(b[0]), "r"(b[1]));
}

__global__ __launch_bounds__(256, 2)
void gemm_bf16_bias(const __nv_bfloat16* __restrict__ A,
                    const __nv_bfloat16* __restrict__ B,
                    const float* __restrict__ bias, float* __restrict__ Y)
{
    extern __shared__ char smem[];
    const uint32_t sb = smem_u32(smem);
    const int t = threadIdx.x;
    const int warp = t >> 5, lane = t & 31;
    const int wm = warp >> 1, wn = warp & 1;          // 4x2 warp grid
    const int row0 = blockIdx.y * CTA_M;
    const int col0 = blockIdx.x * CTA_N;

    // cp.async mapping: per operand per stage = 128 rows x 64B = 512 x 16B segs.
    // thread t -> row = t>>1, segments {(t&1)*2, (t&1)*2+1}
    const int lrow = t >> 1;                // 0..127
    const int seg0 = (t & 1) * 2;           // 0 or 2

    const __nv_bfloat16* gA = A + (size_t)(row0 + lrow) * KSPLIT + seg0 * 8;
    const __nv_bfloat16* gB = B + (size_t)(col0 + lrow) * KSPLIT + seg0 * 8;
    const uint32_t sA0 = sb + lrow * (ASTRIDE * 2) + seg0 * 16;
    const uint32_t sB0 = sA0 + TILE_ELE * 2;

    const int NK = KSPLIT / CTA_K;          // 96

#pragma unroll
    for (int s = 0; s < STAGES - 1; ++s) {
        const uint32_t so = s * STAGE_ELE * 2;
        cp16(sA0 + so,      gA + s * CTA_K);
        cp16(sA0 + so + 16, gA + s * CTA_K + 8);
        cp16(sB0 + so,      gB + s * CTA_K);
        cp16(sB0 + so + 16, gB + s * CTA_K + 8);
        cp_commit();
    }

    float acc[2][8][4];
#pragma unroll
    for (int i = 0; i < 2; ++i)
#pragma unroll
        for (int j = 0; j < 8; ++j)
#pragma unroll
            for (int c = 0; c < 4; ++c) acc[i][j][c] = 0.f;

    // ldmatrix address components
    const int g = lane >> 3, r = lane & 7;
    const int aRow = wm * 32 + (g & 1) * 8 + r;
    const int aK   = (g >> 1) * 8;
    const int bRow = wn * 64 + (g >> 1) * 8 + r;
    const int bK   = (g & 1) * 8;

    for (int ks = 0; ks < NK; ++ks) {
        cp_wait<STAGES - 2>();
        __syncthreads();

        const uint32_t so = (ks % STAGES) * STAGE_ELE * 2;
        const uint32_t sAst = sb + so;
        const uint32_t sBst = sAst + TILE_ELE * 2;

#pragma unroll
        for (int kk = 0; kk < 2; ++kk) {
            uint32_t af[2][4], bf[4][4];
#pragma unroll
            for (int mt = 0; mt < 2; ++mt)
                ldsm4(af[mt], sAst + ((aRow + mt * 16) * ASTRIDE + kk * 16 + aK) * 2);
#pragma unroll
            for (int nn = 0; nn < 4; ++nn)
                ldsm4(bf[nn], sBst + ((bRow + nn * 16) * ASTRIDE + kk * 16 + bK) * 2);
#pragma unroll
            for (int mt = 0; mt < 2; ++mt)
#pragma unroll
                for (int nn = 0; nn < 4; ++nn) {
                    mma16816(acc[mt][nn * 2 + 0], af[mt], &bf[nn][0]);
                    mma16816(acc[mt][nn * 2 + 1], af[mt], &bf[nn][2]);
                }
        }

        const int kn = ks + STAGES - 1;
        if (kn < NK) {
            const uint32_t sn = (kn % STAGES) * STAGE_ELE * 2;
            cp16(sA0 + sn,      gA + kn * CTA_K);
            cp16(sA0 + sn + 16, gA + kn * CTA_K + 8);
            cp16(sB0 + sn,      gB + kn * CTA_K);
            cp16(sB0 + sn + 16, gB + kn * CTA_K + 8);
        }
        cp_commit();
        __syncthreads();
    }

    // epilogue: bias + fp32 store
    const int mBase = row0 + wm * 32 + (lane >> 2);
    const int nBase = col0 + wn * 64 + (lane & 3) * 2;
#pragma unroll
    for (int mt = 0; mt < 2; ++mt) {
#pragma unroll
        for (int nt = 0; nt < 8; ++nt) {
            const int gcol = nBase + nt * 8;
            const float2 bb = *(const float2*)&bias[gcol];
            const int grow = mBase + mt * 16;
            float2 o0, o1;
            o0.x = acc[mt][nt][0] + bb.x;
            o0.y = acc[mt][nt][1] + bb.y;
            o1.x = acc[mt][nt][2] + bb.x;
            o1.y = acc[mt][nt][3] + bb.y;
            *(float2*)&Y[(size_t)grow * DMODEL + gcol]       = o0;
            *(float2*)&Y[(size_t)(grow + 8) * DMODEL + gcol] = o1;
        }
    }
}

// ---------------------------------------------------------------------------
// Flash attention, fp32 (unchanged)
// ---------------------------------------------------------------------------
#define QT 64
#define KT 64
#define QS_STR 65
#define KS_STR 65
#define PS_STR 65
#define VS_STR 68
#define SMEM_FLOATS (64*QS_STR + 64*KS_STR + 64*PS_STR + 64*VS_STR)

__global__ __launch_bounds__(256)
void flash_attn(const float* __restrict__ Qb, const float* __restrict__ Kb,
                const float* __restrict__ Vb, const int* __restrict__ mask,
                float* __restrict__ Cb)
{
    extern __shared__ float sm[];
    float* Qs = sm;
    float* Ks = Qs + 64 * QS_STR;
    float* Ps = Ks + 64 * KS_STR;
    float* Vs = Ps + 64 * PS_STR;

    const int tid = threadIdx.x;
    const int tx = tid & 15;
    const int ty = tid >> 4;
    const int bh = blockIdx.y;
    const int b  = bh >> 4;
    const int h  = bh & 15;
    const int q0 = blockIdx.x * QT;

    const float* Qptr = Qb + ((size_t)(b * SEQ + q0)) * DMODEL + h * DHEAD;

    for (int i = tid; i < 64 * 16; i += 256) {
        const int r  = i >> 4;
        const int c4 = (i & 15) * 4;
        float4 v = *(const float4*)(Qptr + (size_t)r * DMODEL + c4);
        float* dst = &Qs[r * QS_STR + c4];
        dst[0] = v.x; dst[1] = v.y; dst[2] = v.z; dst[3] = v.w;
    }

    float mrow[4], lrow[4], acc[4][4];
#pragma unroll
    for (int i = 0; i < 4; ++i) {
        mrow[i] = -INFINITY; lrow[i] = 0.f;
#pragma unroll
        for (int j = 0; j < 4; ++j) acc[i][j] = 0.f;
    }
    __syncthreads();

    for (int kt = 0; kt < SEQ / KT; ++kt) {
        const int k0 = kt * KT;
        const float* Kptr = Kb + ((size_t)(b * SEQ + k0)) * DMODEL + h * DHEAD;
        const float* Vptr = Vb + ((size_t)(b * SEQ + k0)) * DMODEL + h * DHEAD;

        for (int i = tid; i < 64 * 16; i += 256) {
            const int r  = i >> 4;
            const int c4 = (i & 15) * 4;
            float4 kv = *(const float4*)(Kptr + (size_t)r * DMODEL + c4);
            float* kd = &Ks[r * KS_STR + c4];
            kd[0] = kv.x; kd[1] = kv.y; kd[2] = kv.z; kd[3] = kv.w;
            float4 vv = *(const float4*)(Vptr + (size_t)r * DMODEL + c4);
            float* vd = &Vs[r * VS_STR + c4];
            vd[0] = vv.x; vd[1] = vv.y; vd[2] = vv.z; vd[3] = vv.w;
        }
        __syncthreads();

        float s[4][4];
#pragma unroll
        for (int i = 0; i < 4; ++i)
#pragma unroll
            for (int j = 0; j < 4; ++j) s[i][j] = 0.f;

#pragma unroll 4
        for (int d = 0; d < DHEAD; ++d) {
            float qv[4], kv[4];
#pragma unroll
            for (int i = 0; i < 4; ++i) qv[i] = Qs[(ty * 4 + i) * QS_STR + d];
#pragma unroll
            for (int j = 0; j < 4; ++j) kv[j] = Ks[(tx * 4 + j) * KS_STR + d];
#pragma unroll
            for (int i = 0; i < 4; ++i)
#pragma unroll
                for (int j = 0; j < 4; ++j)
                    s[i][j] = fmaf(qv[i], kv[j], s[i][j]);
        }

#pragma unroll
        for (int i = 0; i < 4; ++i) {
            const int qrow = q0 + ty * 4 + i;
#pragma unroll
            for (int j = 0; j < 4; ++j) {
                const int kcol = k0 + tx * 4 + j;
                const int mv = mask[(size_t)qrow * SEQ + kcol];
                s[i][j] = (mv != 0) ? s[i][j] * 0.125f : -1e9f;
            }
        }

        float rmax[4];
#pragma unroll
        for (int i = 0; i < 4; ++i) {
            float v = fmaxf(fmaxf(s[i][0], s[i][1]), fmaxf(s[i][2], s[i][3]));
#pragma unroll
            for (int off = 8; off > 0; off >>= 1)
                v = fmaxf(v, __shfl_xor_sync(0xffffffffu, v, off, 16));
            rmax[i] = v;
        }

        float scale[4];
#pragma unroll
        for (int i = 0; i < 4; ++i) {
            const float mnew = fmaxf(mrow[i], rmax[i]);
            scale[i] = __expf(mrow[i] - mnew);
            mrow[i]  = mnew;
        }

        float rsum[4];
#pragma unroll
        for (int i = 0; i < 4; ++i) {
            float sum = 0.f;
#pragma unroll
            for (int j = 0; j < 4; ++j) {
                const float p = __expf(s[i][j] - mrow[i]);
                s[i][j] = p;
                sum += p;
            }
#pragma unroll
            for (int off = 8; off > 0; off >>= 1)
                sum += __shfl_xor_sync(0xffffffffu, sum, off, 16);
            rsum[i] = sum;
        }

#pragma unroll
        for (int i = 0; i < 4; ++i) {
            lrow[i] = lrow[i] * scale[i] + rsum[i];
#pragma unroll
            for (int j = 0; j < 4; ++j) acc[i][j] *= scale[i];
        }

#pragma unroll
        for (int i = 0; i < 4; ++i)
#pragma unroll
            for (int j = 0; j < 4; ++j)
                Ps[(ty * 4 + i) * PS_STR + tx * 4 + j] = s[i][j];
        __syncthreads();

#pragma unroll 4
        for (int k = 0; k < KT; ++k) {
            float pv[4];
#pragma unroll
            for (int i = 0; i < 4; ++i) pv[i] = Ps[(ty * 4 + i) * PS_STR + k];
            float4 vv = *(const float4*)&Vs[k * VS_STR + tx * 4];
            const float vj[4] = {vv.x, vv.y, vv.z, vv.w};
#pragma unroll
            for (int i = 0; i < 4; ++i)
#pragma unroll
                for (int j = 0; j < 4; ++j)
                    acc[i][j] = fmaf(pv[i], vj[j], acc[i][j]);
        }
        __syncthreads();
    }

#pragma unroll
    for (int i = 0; i < 4; ++i) {
        const float inv = 1.0f / lrow[i];
        const int row = b * SEQ + q0 + ty * 4 + i;
        float4 o;
        o.x = acc[i][0] * inv;
        o.y = acc[i][1] * inv;
        o.z = acc[i][2] * inv;
        o.w = acc[i][3] * inv;
        *(float4*)(Cb + (size_t)row * DMODEL + h * DHEAD + tx * 4) = o;
    }
}

// ---------------------------------------------------------------------------
extern "C" void kernel_launch(void* const* d_in, const int* in_sizes, int n_in,
                              void* d_out, int out_size)
{
    const float* q    = (const float*)d_in[0];
    const float* k    = (const float*)d_in[1];
    const float* v    = (const float*)d_in[2];
    const int*   mask = (const int*)  d_in[3];
    const float* Wq   = (const float*)d_in[4];
    const float* bq   = (const float*)d_in[5];
    const float* Wk   = (const float*)d_in[6];
    const float* bk   = (const float*)d_in[7];
    const float* Wv   = (const float*)d_in[8];
    const float* bv   = (const float*)d_in[9];
    const float* Wo   = (const float*)d_in[10];
    const float* bo   = (const float*)d_in[11];
    float* out = (float*)d_out;

    float *Qb, *Kb, *Vb, *Cb;
    __nv_bfloat16 *Xs, *Ws;
    cudaGetSymbolAddress((void**)&Qb, g_Q);
    cudaGetSymbolAddress((void**)&Kb, g_K);
    cudaGetSymbolAddress((void**)&Vb, g_V);
    cudaGetSymbolAddress((void**)&Cb, g_C);
    cudaGetSymbolAddress((void**)&Xs, g_Xs);
    cudaGetSymbolAddress((void**)&Ws, g_Ws);

    cudaFuncSetAttribute(gemm_bf16_bias, cudaFuncAttributeMaxDynamicSharedMemorySize,
                         GEMM_SMEM);
    static const size_t smemBytes = SMEM_FLOATS * sizeof(float);
    cudaFuncSetAttribute(flash_attn, cudaFuncAttributeMaxDynamicSharedMemorySize,
                         (int)smemBytes);

    const int n4x = MROWS * DMODEL / 4;     // 1M float4
    const int n4w = DMODEL * DMODEL / 4;    // 256K float4
    const dim3 gemmGrid(DMODEL / CTA_N, MROWS / CTA_M);   // (8, 32)

    // Q projection
    split3<1><<<n4x / 256, 256>>>(q,  Xs, n4x);   // X: [hi | lo | hi]
    split3<0><<<n4w / 256, 256>>>(Wq, Ws, n4w);   // W: [hi | hi | lo]
    gemm_bf16_bias<<<gemmGrid, 256, GEMM_SMEM>>>(Xs, Ws, bq, Qb);
    // K projection
    split3<1><<<n4x / 256, 256>>>(k,  Xs, n4x);
    split3<0><<<n4w / 256, 256>>>(Wk, Ws, n4w);
    gemm_bf16_bias<<<gemmGrid, 256, GEMM_SMEM>>>(Xs, Ws, bk, Kb);
    // V projection
    split3<1><<<n4x / 256, 256>>>(v,  Xs, n4x);
    split3<0><<<n4w / 256, 256>>>(Wv, Ws, n4w);
    gemm_bf16_bias<<<gemmGrid, 256, GEMM_SMEM>>>(Xs, Ws, bv, Vb);

    // attention
    flash_attn<<<dim3(SEQ / QT, BATCH * NHEAD), 256, smemBytes>>>(Qb, Kb, Vb, mask, Cb);

    // output projection
    split3<1><<<n4x / 256, 256>>>(Cb, Xs, n4x);
    split3<0><<<n4w / 256, 256>>>(Wo, Ws, n4w);
    gemm_bf16_bias<<<gemmGrid, 256, GEMM_SMEM>>>(Xs, Ws, bo, out);
}

// round 6
// speedup vs baseline: 2.7701x; 2.0934x over previous
#include <cuda_runtime.h>
#include <cuda_bf16.h>
#include <math.h>
#include <stdint.h>

#define BATCH  2
#define SEQ    2048
#define DMODEL 1024
#define NHEAD  16
#define DHEAD  64
#define MROWS  (BATCH*SEQ)   // 4096
#define KSPLIT 3072          // [hi | lo | hi] along K

// ---------------------------------------------------------------------------
// Scratch (__device__ globals; no allocation allowed)
// ---------------------------------------------------------------------------
__device__ float g_C[MROWS*DMODEL];
__device__ __nv_bfloat16 g_Xs[MROWS*KSPLIT];    // A'' = [hi | lo | hi]
__device__ __nv_bfloat16 g_Ws[DMODEL*KSPLIT];   // B'' = [hi | hi | lo]
// head-major projected tensors: [b][h][s][64], hi/lo split
__device__ __nv_bfloat16 g_Qh_hi[MROWS*DMODEL];
__device__ __nv_bfloat16 g_Qh_lo[MROWS*DMODEL];
__device__ __nv_bfloat16 g_Kh_hi[MROWS*DMODEL];
__device__ __nv_bfloat16 g_Kh_lo[MROWS*DMODEL];
__device__ __nv_bfloat16 g_Vh_hi[MROWS*DMODEL];
__device__ __nv_bfloat16 g_Vh_lo[MROWS*DMODEL];

__device__ __forceinline__ uint32_t smem_u32(const void* p) {
    uint32_t a;
    asm("{ .reg .u64 t; cvta.to.shared.u64 t, %1; cvt.u32.u64 %0, t; }" : "=r"(a) : "l"(p));
    return a;
}

// ---------------------------------------------------------------------------
// fp32 -> split-bf16 expansion (GEMM inputs)
// ---------------------------------------------------------------------------
template<int LO_AT_MID>
__global__ void split3(const float* __restrict__ src,
                       __nv_bfloat16* __restrict__ dst, int n4)
{
    int i = blockIdx.x * blockDim.x + threadIdx.x;
    if (i >= n4) return;
    const int row = i >> 8;
    const int col = (i & 255) * 4;
    float4 x = ((const float4*)src)[i];
    __nv_bfloat16 h0 = __float2bfloat16_rn(x.x);
    __nv_bfloat16 h1 = __float2bfloat16_rn(x.y);
    __nv_bfloat16 h2 = __float2bfloat16_rn(x.z);
    __nv_bfloat16 h3 = __float2bfloat16_rn(x.w);
    __nv_bfloat16 l0 = __float2bfloat16_rn(x.x - __bfloat162float(h0));
    __nv_bfloat16 l1 = __float2bfloat16_rn(x.y - __bfloat162float(h1));
    __nv_bfloat16 l2 = __float2bfloat16_rn(x.z - __bfloat162float(h2));
    __nv_bfloat16 l3 = __float2bfloat16_rn(x.w - __bfloat162float(h3));
    __nv_bfloat162 hp0 = __halves2bfloat162(h0, h1);
    __nv_bfloat162 hp1 = __halves2bfloat162(h2, h3);
    __nv_bfloat162 lp0 = __halves2bfloat162(l0, l1);
    __nv_bfloat162 lp1 = __halves2bfloat162(l2, l3);
    uint2 hp = make_uint2(*(uint32_t*)&hp0, *(uint32_t*)&hp1);
    uint2 lp = make_uint2(*(uint32_t*)&lp0, *(uint32_t*)&lp1);
    __nv_bfloat16* base = dst + (size_t)row * KSPLIT + col;
    *(uint2*)(base)        = hp;
    *(uint2*)(base + 1024) = LO_AT_MID ? lp : hp;
    *(uint2*)(base + 2048) = LO_AT_MID ? hp : lp;
}

// ---------------------------------------------------------------------------
// mma.sync primitives
// ---------------------------------------------------------------------------
__device__ __forceinline__ void cp16(uint32_t smem, const void* gmem) {
    asm volatile("cp.async.cg.shared.global [%0], [%1], 16;" :: "r"(smem), "l"(gmem));
}
__device__ __forceinline__ void cp_commit() { asm volatile("cp.async.commit_group;"); }
template<int N> __device__ __forceinline__ void cp_wait() {
    asm volatile("cp.async.wait_group %0;" :: "n"(N));
}
__device__ __forceinline__ void ldsm4(uint32_t* r, uint32_t addr) {
    asm volatile("ldmatrix.sync.aligned.m8n8.x4.shared.b16 {%0,%1,%2,%3}, [%4];"
        : "=r"(r[0]), "=r"(r[1]), "=r"(r[2]), "=r"(r[3]) : "r"(addr));
}
__device__ __forceinline__ void ldsm4t(uint32_t* r, uint32_t addr) {
    asm volatile("ldmatrix.sync.aligned.m8n8.x4.trans.shared.b16 {%0,%1,%2,%3}, [%4];"
        : "=r"(r[0]), "=r"(r[1]), "=r"(r[2]), "=r"(r[3]) : "r"(addr));
}
__device__ __forceinline__ void mma16816(float* d, const uint32_t* a, const uint32_t* b) {
    asm volatile(
        "mma.sync.aligned.m16n8k16.row.col.f32.bf16.bf16.f32 "
        "{%0,%1,%2,%3}, {%4,%5,%6,%7}, {%8,%9}, {%0,%1,%2,%3};"
        : "+f"(d[0]), "+f"(d[1]), "+f"(d[2]), "+f"(d[3])
        : "r"(a[0]), "r"(a[1]), "r"(a[2]), "r"(a[3]), "r"(b[0]), "r"(b[1]));
}
__device__ __forceinline__ uint32_t packbf2(float lo, float hi) {
    uint32_t r;
    asm("cvt.rn.bf16x2.f32 %0, %1, %2;" : "=r"(r) : "f"(hi), "f"(lo));
    return r;
}

// ---------------------------------------------------------------------------
// bf16 mma GEMM: Y = A''[M,3072] @ B''[1024,3072]^T + bias
// HEADS_OUT=1: write split-bf16 head-major [b][h][s][64]; else fp32 row-major.
// ---------------------------------------------------------------------------
#define CTA_M   128
#define CTA_N   128
#define CTA_K   32
#define STAGES  4
#define ASTRIDE 40
#define TILE_ELE  (128 * ASTRIDE)
#define STAGE_ELE (2 * TILE_ELE)
#define GEMM_SMEM (STAGES * STAGE_ELE * 2)

template<int HEADS_OUT>
__global__ __launch_bounds__(256, 2)
void gemm_bf16_bias(const __nv_bfloat16* __restrict__ A,
                    const __nv_bfloat16* __restrict__ B,
                    const float* __restrict__ bias, float* __restrict__ Y,
                    __nv_bfloat16* __restrict__ Yhi, __nv_bfloat16* __restrict__ Ylo)
{
    extern __shared__ char smem[];
    const uint32_t sb = smem_u32(smem);
    const int t = threadIdx.x;
    const int warp = t >> 5, lane = t & 31;
    const int wm = warp >> 1, wn = warp & 1;
    const int row0 = blockIdx.y * CTA_M;
    const int col0 = blockIdx.x * CTA_N;

    const int lrow = t >> 1;
    const int seg0 = (t & 1) * 2;

    const __nv_bfloat16* gA = A + (size_t)(row0 + lrow) * KSPLIT + seg0 * 8;
    const __nv_bfloat16* gB = B + (size_t)(col0 + lrow) * KSPLIT + seg0 * 8;
    const uint32_t sA0 = sb + lrow * (ASTRIDE * 2) + seg0 * 16;
    const uint32_t sB0 = sA0 + TILE_ELE * 2;

    const int NK = KSPLIT / CTA_K;

#pragma unroll
    for (int s = 0; s < STAGES - 1; ++s) {
        const uint32_t so = s * STAGE_ELE * 2;
        cp16(sA0 + so,      gA + s * CTA_K);
        cp16(sA0 + so + 16, gA + s * CTA_K + 8);
        cp16(sB0 + so,      gB + s * CTA_K);
        cp16(sB0 + so + 16, gB + s * CTA_K + 8);
        cp_commit();
    }

    float acc[2][8][4];
#pragma unroll
    for (int i = 0; i < 2; ++i)
#pragma unroll
        for (int j = 0; j < 8; ++j)
#pragma unroll
            for (int c = 0; c < 4; ++c) acc[i][j][c] = 0.f;

    const int g = lane >> 3, r = lane & 7;
    const int aRow = wm * 32 + (g & 1) * 8 + r;
    const int aK   = (g >> 1) * 8;
    const int bRow = wn * 64 + (g >> 1) * 8 + r;
    const int bK   = (g & 1) * 8;

    for (int ks = 0; ks < NK; ++ks) {
        cp_wait<STAGES - 2>();
        __syncthreads();

        const uint32_t so = (ks % STAGES) * STAGE_ELE * 2;
        const uint32_t sAst = sb + so;
        const uint32_t sBst = sAst + TILE_ELE * 2;

#pragma unroll
        for (int kk = 0; kk < 2; ++kk) {
            uint32_t af[2][4], bf[4][4];
#pragma unroll
            for (int mt = 0; mt < 2; ++mt)
                ldsm4(af[mt], sAst + ((aRow + mt * 16) * ASTRIDE + kk * 16 + aK) * 2);
#pragma unroll
            for (int nn = 0; nn < 4; ++nn)
                ldsm4(bf[nn], sBst + ((bRow + nn * 16) * ASTRIDE + kk * 16 + bK) * 2);
#pragma unroll
            for (int mt = 0; mt < 2; ++mt)
#pragma unroll
                for (int nn = 0; nn < 4; ++nn) {
                    mma16816(acc[mt][nn * 2 + 0], af[mt], &bf[nn][0]);
                    mma16816(acc[mt][nn * 2 + 1], af[mt], &bf[nn][2]);
                }
        }

        const int kn = ks + STAGES - 1;
        if (kn < NK) {
            const uint32_t sn = (kn % STAGES) * STAGE_ELE * 2;
            cp16(sA0 + sn,      gA + kn * CTA_K);
            cp16(sA0 + sn + 16, gA + kn * CTA_K + 8);
            cp16(sB0 + sn,      gB + kn * CTA_K);
            cp16(sB0 + sn + 16, gB + kn * CTA_K + 8);
        }
        cp_commit();
        __syncthreads();
    }

    const int mBase = row0 + wm * 32 + (lane >> 2);
    const int nBase = col0 + wn * 64 + (lane & 3) * 2;
#pragma unroll
    for (int mt = 0; mt < 2; ++mt) {
#pragma unroll
        for (int nt = 0; nt < 8; ++nt) {
            const int gcol = nBase + nt * 8;
            const float2 bb = *(const float2*)&bias[gcol];
            float v0a = acc[mt][nt][0] + bb.x;
            float v0b = acc[mt][nt][1] + bb.y;
            float v1a = acc[mt][nt][2] + bb.x;
            float v1b = acc[mt][nt][3] + bb.y;
            const int grow0 = mBase + mt * 16;
            const int grow1 = grow0 + 8;
            if (HEADS_OUT) {
                const int h = gcol >> 6, c = gcol & 63;
                // row -> (b, s); dst = ((b*16+h)*2048 + s)*64 + c
                const int b0 = grow0 >> 11, s0 = grow0 & 2047;
                const int b1 = grow1 >> 11, s1 = grow1 & 2047;
                const size_t d0 = ((size_t)(b0 * 16 + h) * 2048 + s0) * 64 + c;
                const size_t d1 = ((size_t)(b1 * 16 + h) * 2048 + s1) * 64 + c;
                __nv_bfloat16 h0a = __float2bfloat16_rn(v0a);
                __nv_bfloat16 h0b = __float2bfloat16_rn(v0b);
                __nv_bfloat16 h1a = __float2bfloat16_rn(v1a);
                __nv_bfloat16 h1b = __float2bfloat16_rn(v1b);
                __nv_bfloat162 hp0 = __halves2bfloat162(h0a, h0b);
                __nv_bfloat162 hp1 = __halves2bfloat162(h1a, h1b);
                __nv_bfloat162 lp0 = __halves2bfloat162(
                    __float2bfloat16_rn(v0a - __bfloat162float(h0a)),
                    __float2bfloat16_rn(v0b - __bfloat162float(h0b)));
                __nv_bfloat162 lp1 = __halves2bfloat162(
                    __float2bfloat16_rn(v1a - __bfloat162float(h1a)),
                    __float2bfloat16_rn(v1b - __bfloat162float(h1b)));
                *(uint32_t*)(Yhi + d0) = *(uint32_t*)&hp0;
                *(uint32_t*)(Yhi + d1) = *(uint32_t*)&hp1;
                *(uint32_t*)(Ylo + d0) = *(uint32_t*)&lp0;
                *(uint32_t*)(Ylo + d1) = *(uint32_t*)&lp1;
            } else {
                *(float2*)&Y[(size_t)grow0 * DMODEL + gcol] = make_float2(v0a, v0b);
                *(float2*)&Y[(size_t)grow1 * DMODEL + gcol] = make_float2(v1a, v1b);
            }
        }
    }
}

// ---------------------------------------------------------------------------
// Flash attention on HMMA.
// Q-tile 128 (4 warps x m32), K-tile 64. QK^T: 3-term split bf16.
// PV: P bf16 (from S accums), V hi/lo (2 terms).
// smem: Qhi/Qlo [128][72], Khi/Klo/Vhi/Vlo [64][72]  (72 bf16 = 144B rows)
// ---------------------------------------------------------------------------
#define FS_STR   72
#define FS_Q     (128 * FS_STR)                  // elems per Q array
#define FS_KV    (64 * FS_STR)
#define SM_QHI   0
#define SM_QLO   (SM_QHI + FS_Q)
#define SM_KHI   (SM_QLO + FS_Q)
#define SM_KLO   (SM_KHI + FS_KV)
#define SM_VHI   (SM_KLO + FS_KV)
#define SM_VLO   (SM_VHI + FS_KV)
#define FLASH_SMEM ((SM_VLO + FS_KV) * 2)        // bytes = 73728

__global__ __launch_bounds__(128, 2)
void flash_mma(const __nv_bfloat16* __restrict__ Qhi_g,
               const __nv_bfloat16* __restrict__ Qlo_g,
               const __nv_bfloat16* __restrict__ Khi_g,
               const __nv_bfloat16* __restrict__ Klo_g,
               const __nv_bfloat16* __restrict__ Vhi_g,
               const __nv_bfloat16* __restrict__ Vlo_g,
               const int* __restrict__ mask, float* __restrict__ Cb)
{
    extern __shared__ char smem[];
    const uint32_t sb = smem_u32(smem);
    const int t = threadIdx.x;
    const int warp = t >> 5, lane = t & 31;
    const int grp = lane >> 2, tg = lane & 3;
    const int bh = blockIdx.y;                  // b*16 + h
    const int b  = bh >> 4, h = bh & 15;
    const int q0 = blockIdx.x * 128;

    const size_t headOff = (size_t)bh * SEQ * DHEAD;
    const __nv_bfloat16* Qhg = Qhi_g + headOff;
    const __nv_bfloat16* Qlg = Qlo_g + headOff;
    const __nv_bfloat16* Khg = Khi_g + headOff;
    const __nv_bfloat16* Klg = Klo_g + headOff;
    const __nv_bfloat16* Vhg = Vhi_g + headOff;
    const __nv_bfloat16* Vlg = Vlo_g + headOff;

    // load Q tile (128 rows x 128B) hi+lo: 8 chunks/thread/array
#pragma unroll
    for (int i = 0; i < 8; ++i) {
        const int id = i * 128 + t;
        const int row = id >> 3, seg = id & 7;
        cp16(sb + SM_QHI * 2 + row * 144 + seg * 16,
             (const char*)Qhg + (size_t)(q0 + row) * 128 + seg * 16);
        cp16(sb + SM_QLO * 2 + row * 144 + seg * 16,
             (const char*)Qlg + (size_t)(q0 + row) * 128 + seg * 16);
    }
    cp_commit();

    // per-thread fragment index helpers
    const int g2 = lane >> 3, r8 = lane & 7;
    const int arow = (g2 & 1) * 8 + r8;         // A-frag / V-trans row
    const int akoff = (lane >> 4) * 8;          // A-frag k offset / V-trans col offset
    const int brow = (lane >> 4) * 8 + r8;      // B-frag row
    const int bkoff = (g2 & 1) * 8;             // B-frag k offset

    float ctx[2][8][4];
    float mrow[2][2], lrow[2][2];
#pragma unroll
    for (int mt = 0; mt < 2; ++mt) {
        mrow[mt][0] = -INFINITY; mrow[mt][1] = -INFINITY;
        lrow[mt][0] = 0.f; lrow[mt][1] = 0.f;
#pragma unroll
        for (int j = 0; j < 8; ++j)
#pragma unroll
            for (int c = 0; c < 4; ++c) ctx[mt][j][c] = 0.f;
    }

    const int qr0 = q0 + warp * 32 + grp;       // mt row bases (mt*16, +8)

    for (int kt = 0; kt < SEQ / 64; ++kt) {
        const int k0 = kt * 64;
        __syncthreads();                         // prior reads done before overwrite
        // load K,V hi/lo tiles: 64 rows x 8 segs = 512 chunks -> 4/thread/array
#pragma unroll
        for (int i = 0; i < 4; ++i) {
            const int id = i * 128 + t;
            const int row = id >> 3, seg = id & 7;
            const size_t go = (size_t)(k0 + row) * 128 + seg * 16;
            const uint32_t so = row * 144 + seg * 16;
            cp16(sb + SM_KHI * 2 + so, (const char*)Khg + go);
            cp16(sb + SM_KLO * 2 + so, (const char*)Klg + go);
            cp16(sb + SM_VHI * 2 + so, (const char*)Vhg + go);
            cp16(sb + SM_VLO * 2 + so, (const char*)Vlg + go);
        }
        cp_commit();
        cp_wait<0>();
        __syncthreads();

        // ---- S = Q K^T (3-term split) ----
        float S[2][8][4];
#pragma unroll
        for (int mt = 0; mt < 2; ++mt)
#pragma unroll
            for (int j = 0; j < 8; ++j)
#pragma unroll
                for (int c = 0; c < 4; ++c) S[mt][j][c] = 0.f;

#pragma unroll
        for (int kk = 0; kk < 4; ++kk) {
            uint32_t aQh[2][4], aQl[2][4];
#pragma unroll
            for (int mt = 0; mt < 2; ++mt) {
                const uint32_t qa = (warp * 32 + mt * 16 + arow) * FS_STR + kk * 16 + akoff;
                ldsm4(aQh[mt], sb + (SM_QHI + qa) * 2);
                ldsm4(aQl[mt], sb + (SM_QLO + qa) * 2);
            }
#pragma unroll
            for (int nt = 0; nt < 4; ++nt) {
                uint32_t bh4[4], bl4[4];
                const uint32_t ka = (nt * 16 + brow) * FS_STR + kk * 16 + bkoff;
                ldsm4(bh4, sb + (SM_KHI + ka) * 2);
                ldsm4(bl4, sb + (SM_KLO + ka) * 2);
#pragma unroll
                for (int mt = 0; mt < 2; ++mt) {
                    mma16816(S[mt][nt * 2 + 0], aQh[mt], &bh4[0]);
                    mma16816(S[mt][nt * 2 + 1], aQh[mt], &bh4[2]);
                    mma16816(S[mt][nt * 2 + 0], aQl[mt], &bh4[0]);
                    mma16816(S[mt][nt * 2 + 1], aQl[mt], &bh4[2]);
                    mma16816(S[mt][nt * 2 + 0], aQh[mt], &bl4[0]);
                    mma16816(S[mt][nt * 2 + 1], aQh[mt], &bl4[2]);
                }
            }
        }

        // ---- mask + online softmax + pack P ----
        uint32_t Pf[2][4][4];
#pragma unroll
        for (int mt = 0; mt < 2; ++mt) {
            const int row0 = qr0 + mt * 16;
            const int row1 = row0 + 8;
            float mx0 = -INFINITY, mx1 = -INFINITY;
#pragma unroll
            for (int j = 0; j < 8; ++j) {
                const int kcol = k0 + j * 8 + tg * 2;
                const int2 mv0 = *(const int2*)&mask[(size_t)row0 * SEQ + kcol];
                const int2 mv1 = *(const int2*)&mask[(size_t)row1 * SEQ + kcol];
                S[mt][j][0] = mv0.x ? S[mt][j][0] * 0.125f : -1e9f;
                S[mt][j][1] = mv0.y ? S[mt][j][1] * 0.125f : -1e9f;
                S[mt][j][2] = mv1.x ? S[mt][j][2] * 0.125f : -1e9f;
                S[mt][j][3] = mv1.y ? S[mt][j][3] * 0.125f : -1e9f;
                mx0 = fmaxf(mx0, fmaxf(S[mt][j][0], S[mt][j][1]));
                mx1 = fmaxf(mx1, fmaxf(S[mt][j][2], S[mt][j][3]));
            }
            mx0 = fmaxf(mx0, __shfl_xor_sync(0xffffffffu, mx0, 1));
            mx0 = fmaxf(mx0, __shfl_xor_sync(0xffffffffu, mx0, 2));
            mx1 = fmaxf(mx1, __shfl_xor_sync(0xffffffffu, mx1, 1));
            mx1 = fmaxf(mx1, __shfl_xor_sync(0xffffffffu, mx1, 2));

            const float mn0 = fmaxf(mrow[mt][0], mx0);
            const float mn1 = fmaxf(mrow[mt][1], mx1);
            const float sc0 = __expf(mrow[mt][0] - mn0);
            const float sc1 = __expf(mrow[mt][1] - mn1);
            mrow[mt][0] = mn0; mrow[mt][1] = mn1;

            float sum0 = 0.f, sum1 = 0.f;
#pragma unroll
            for (int j = 0; j < 8; ++j) {
                S[mt][j][0] = __expf(S[mt][j][0] - mn0);
                S[mt][j][1] = __expf(S[mt][j][1] - mn0);
                S[mt][j][2] = __expf(S[mt][j][2] - mn1);
                S[mt][j][3] = __expf(S[mt][j][3] - mn1);
                sum0 += S[mt][j][0] + S[mt][j][1];
                sum1 += S[mt][j][2] + S[mt][j][3];
#pragma unroll
                for (int c = 0; c < 4; ++c)
                    ctx[mt][j][c] *= (c < 2) ? sc0 : sc1;
            }
            sum0 += __shfl_xor_sync(0xffffffffu, sum0, 1);
            sum0 += __shfl_xor_sync(0xffffffffu, sum0, 2);
            sum1 += __shfl_xor_sync(0xffffffffu, sum1, 1);
            sum1 += __shfl_xor_sync(0xffffffffu, sum1, 2);
            lrow[mt][0] = lrow[mt][0] * sc0 + sum0;
            lrow[mt][1] = lrow[mt][1] * sc1 + sum1;

#pragma unroll
            for (int ks = 0; ks < 4; ++ks) {
                Pf[mt][ks][0] = packbf2(S[mt][2 * ks][0],     S[mt][2 * ks][1]);
                Pf[mt][ks][1] = packbf2(S[mt][2 * ks][2],     S[mt][2 * ks][3]);
                Pf[mt][ks][2] = packbf2(S[mt][2 * ks + 1][0], S[mt][2 * ks + 1][1]);
                Pf[mt][ks][3] = packbf2(S[mt][2 * ks + 1][2], S[mt][2 * ks + 1][3]);
            }
        }

        // ---- ctx += P (Vhi + Vlo) ----
#pragma unroll
        for (int ks = 0; ks < 4; ++ks) {
#pragma unroll
            for (int nt = 0; nt < 4; ++nt) {
                uint32_t vh[4], vl[4];
                const uint32_t va = (ks * 16 + arow) * FS_STR + nt * 16 + akoff;
                ldsm4t(vh, sb + (SM_VHI + va) * 2);
                ldsm4t(vl, sb + (SM_VLO + va) * 2);
#pragma unroll
                for (int mt = 0; mt < 2; ++mt) {
                    mma16816(ctx[mt][nt * 2 + 0], Pf[mt][ks], &vh[0]);
                    mma16816(ctx[mt][nt * 2 + 1], Pf[mt][ks], &vh[2]);
                    mma16816(ctx[mt][nt * 2 + 0], Pf[mt][ks], &vl[0]);
                    mma16816(ctx[mt][nt * 2 + 1], Pf[mt][ks], &vl[2]);
                }
            }
        }
    }

    // ---- epilogue: normalize, write fp32 context [b][s][1024] ----
#pragma unroll
    for (int mt = 0; mt < 2; ++mt) {
        const float inv0 = 1.0f / lrow[mt][0];
        const float inv1 = 1.0f / lrow[mt][1];
        const int row0 = qr0 + mt * 16;
        const int row1 = row0 + 8;
        float* c0 = Cb + (size_t)(b * SEQ + row0) * DMODEL + h * DHEAD;
        float* c1 = Cb + (size_t)(b * SEQ + row1) * DMODEL + h * DHEAD;
#pragma unroll
        for (int j = 0; j < 8; ++j) {
            const int d = j * 8 + tg * 2;
            *(float2*)(c0 + d) = make_float2(ctx[mt][j][0] * inv0, ctx[mt][j][1] * inv0);
            *(float2*)(c1 + d) = make_float2(ctx[mt][j][2] * inv1, ctx[mt][j][3] * inv1);
        }
    }
}

// ---------------------------------------------------------------------------
extern "C" void kernel_launch(void* const* d_in, const int* in_sizes, int n_in,
                              void* d_out, int out_size)
{
    const float* q    = (const float*)d_in[0];
    const float* k    = (const float*)d_in[1];
    const float* v    = (const float*)d_in[2];
    const int*   mask = (const int*)  d_in[3];
    const float* Wq   = (const float*)d_in[4];
    const float* bq   = (const float*)d_in[5];
    const float* Wk   = (const float*)d_in[6];
    const float* bk   = (const float*)d_in[7];
    const float* Wv   = (const float*)d_in[8];
    const float* bv   = (const float*)d_in[9];
    const float* Wo   = (const float*)d_in[10];
    const float* bo   = (const float*)d_in[11];
    float* out = (float*)d_out;

    float *Cb;
    __nv_bfloat16 *Xs, *Ws, *Qhh, *Qhl, *Khh, *Khl, *Vhh, *Vhl;
    cudaGetSymbolAddress((void**)&Cb, g_C);
    cudaGetSymbolAddress((void**)&Xs, g_Xs);
    cudaGetSymbolAddress((void**)&Ws, g_Ws);
    cudaGetSymbolAddress((void**)&Qhh, g_Qh_hi);
    cudaGetSymbolAddress((void**)&Qhl, g_Qh_lo);
    cudaGetSymbolAddress((void**)&Khh, g_Kh_hi);
    cudaGetSymbolAddress((void**)&Khl, g_Kh_lo);
    cudaGetSymbolAddress((void**)&Vhh, g_Vh_hi);
    cudaGetSymbolAddress((void**)&Vhl, g_Vh_lo);

    cudaFuncSetAttribute(gemm_bf16_bias<0>, cudaFuncAttributeMaxDynamicSharedMemorySize, GEMM_SMEM);
    cudaFuncSetAttribute(gemm_bf16_bias<1>, cudaFuncAttributeMaxDynamicSharedMemorySize, GEMM_SMEM);
    cudaFuncSetAttribute(flash_mma, cudaFuncAttributeMaxDynamicSharedMemorySize, FLASH_SMEM);

    const int n4x = MROWS * DMODEL / 4;
    const int n4w = DMODEL * DMODEL / 4;
    const dim3 gemmGrid(DMODEL / CTA_N, MROWS / CTA_M);

    // Q projection -> head-major split bf16
    split3<1><<<n4x / 256, 256>>>(q,  Xs, n4x);
    split3<0><<<n4w / 256, 256>>>(Wq, Ws, n4w);
    gemm_bf16_bias<1><<<gemmGrid, 256, GEMM_SMEM>>>(Xs, Ws, bq, nullptr, Qhh, Qhl);
    // K projection
    split3<1><<<n4x / 256, 256>>>(k,  Xs, n4x);
    split3<0><<<n4w / 256, 256>>>(Wk, Ws, n4w);
    gemm_bf16_bias<1><<<gemmGrid, 256, GEMM_SMEM>>>(Xs, Ws, bk, nullptr, Khh, Khl);
    // V projection
    split3<1><<<n4x / 256, 256>>>(v,  Xs, n4x);
    split3<0><<<n4w / 256, 256>>>(Wv, Ws, n4w);
    gemm_bf16_bias<1><<<gemmGrid, 256, GEMM_SMEM>>>(Xs, Ws, bv, nullptr, Vhh, Vhl);

    // attention (HMMA flash)
    flash_mma<<<dim3(SEQ / 128, BATCH * NHEAD), 128, FLASH_SMEM>>>(
        Qhh, Qhl, Khh, Khl, Vhh, Vhl, mask, Cb);

    // output projection (fp32 out)
    split3<1><<<n4x / 256, 256>>>(Cb, Xs, n4x);
    split3<0><<<n4w / 256, 256>>>(Wo, Ws, n4w);
    gemm_bf16_bias<0><<<gemmGrid, 256, GEMM_SMEM>>>(Xs, Ws, bo, out, nullptr, nullptr);
}

// round 7
// speedup vs baseline: 5.6973x; 2.0567x over previous
#include <cuda_runtime.h>
#include <cuda_fp16.h>
#include <math.h>
#include <stdint.h>

#define BATCH  2
#define SEQ    2048
#define DMODEL 1024
#define NHEAD  16
#define DHEAD  64
#define MROWS  (BATCH*SEQ)   // 4096
#define KDIM   1024

// ---------------------------------------------------------------------------
// Scratch (__device__ globals; no allocation allowed)
// ---------------------------------------------------------------------------
__device__ __half g_Xq[MROWS*DMODEL];
__device__ __half g_Xk[MROWS*DMODEL];
__device__ __half g_Xv[MROWS*DMODEL];
__device__ __half g_W0[DMODEL*DMODEL];
__device__ __half g_W1[DMODEL*DMODEL];
__device__ __half g_W2[DMODEL*DMODEL];
__device__ __half g_W3[DMODEL*DMODEL];
__device__ __half g_Qh[MROWS*DMODEL];   // head-major [b][h][s][64]
__device__ __half g_Kh[MROWS*DMODEL];
__device__ __half g_Vh[MROWS*DMODEL];
__device__ __half g_Ctx[MROWS*DMODEL];  // row-major fp16 context

__device__ __forceinline__ uint32_t smem_u32(const void* p) {
    uint32_t a;
    asm("{ .reg .u64 t; cvta.to.shared.u64 t, %1; cvt.u32.u64 %0, t; }" : "=r"(a) : "l"(p));
    return a;
}

// ---------------------------------------------------------------------------
// fp32 -> fp16 convert, batched over blockIdx.z (up to 4 tensors)
// ---------------------------------------------------------------------------
__global__ void to_half(const float* __restrict__ s0, const float* __restrict__ s1,
                        const float* __restrict__ s2, const float* __restrict__ s3,
                        __half* __restrict__ d0, __half* __restrict__ d1,
                        __half* __restrict__ d2, __half* __restrict__ d3, int n4)
{
    const int z = blockIdx.z;
    const float* s = (z == 0) ? s0 : (z == 1) ? s1 : (z == 2) ? s2 : s3;
    __half*      d = (z == 0) ? d0 : (z == 1) ? d1 : (z == 2) ? d2 : d3;
    int i = blockIdx.x * blockDim.x + threadIdx.x;
    if (i >= n4) return;
    float4 x = ((const float4*)s)[i];
    __half2 a = __floats2half2_rn(x.x, x.y);
    __half2 b = __floats2half2_rn(x.z, x.w);
    ((uint2*)d)[i] = make_uint2(*(uint32_t*)&a, *(uint32_t*)&b);
}

// ---------------------------------------------------------------------------
// mma primitives (fp16)
// ---------------------------------------------------------------------------
__device__ __forceinline__ void cp16(uint32_t smem, const void* gmem) {
    asm volatile("cp.async.cg.shared.global [%0], [%1], 16;" :: "r"(smem), "l"(gmem));
}
__device__ __forceinline__ void cp_commit() { asm volatile("cp.async.commit_group;"); }
template<int N> __device__ __forceinline__ void cp_wait() {
    asm volatile("cp.async.wait_group %0;" :: "n"(N));
}
__device__ __forceinline__ void ldsm4(uint32_t* r, uint32_t addr) {
    asm volatile("ldmatrix.sync.aligned.m8n8.x4.shared.b16 {%0,%1,%2,%3}, [%4];"
        : "=r"(r[0]), "=r"(r[1]), "=r"(r[2]), "=r"(r[3]) : "r"(addr));
}
__device__ __forceinline__ void ldsm4t(uint32_t* r, uint32_t addr) {
    asm volatile("ldmatrix.sync.aligned.m8n8.x4.trans.shared.b16 {%0,%1,%2,%3}, [%4];"
        : "=r"(r[0]), "=r"(r[1]), "=r"(r[2]), "=r"(r[3]) : "r"(addr));
}
__device__ __forceinline__ void mma16816(float* d, const uint32_t* a, const uint32_t* b) {
    asm volatile(
        "mma.sync.aligned.m16n8k16.row.col.f32.f16.f16.f32 "
        "{%0,%1,%2,%3}, {%4,%5,%6,%7}, {%8,%9}, {%0,%1,%2,%3};"
        : "+f"(d[0]), "+f"(d[1]), "+f"(d[2]), "+f"(d[3])
        : "r"(a[0]), "r"(a[1]), "r"(a[2]), "r"(a[3]), "r"(b[0]), "r"(b[1]));
}
__device__ __forceinline__ uint32_t packh2(float lo, float hi) {
    uint32_t r;
    asm("cvt.rn.f16x2.f32 %0, %1, %2;" : "=r"(r) : "f"(hi), "f"(lo));
    return r;
}

// ---------------------------------------------------------------------------
// fp16 mma GEMM: Y[M,1024] = A[M,1024] @ B[1024,1024]^T + bias
// CTA 128x128, K-step 32, 4-stage cp.async pipeline, 8 warps.
// HEADS_OUT=1: z-batched QKV; write fp16 head-major. Else fp32 row-major out.
// ---------------------------------------------------------------------------
#define CTA_M   128
#define CTA_N   128
#define CTA_K   32
#define STAGES  4
#define ASTRIDE 40
#define TILE_ELE  (128 * ASTRIDE)
#define STAGE_ELE (2 * TILE_ELE)
#define GEMM_SMEM (STAGES * STAGE_ELE * 2)

template<int HEADS_OUT>
__global__ __launch_bounds__(256, 2)
void gemm_fp16(const __half* __restrict__ A0, const __half* __restrict__ A1,
               const __half* __restrict__ A2,
               const __half* __restrict__ B0, const __half* __restrict__ B1,
               const __half* __restrict__ B2,
               const float* __restrict__ bias0, const float* __restrict__ bias1,
               const float* __restrict__ bias2,
               __half* __restrict__ H0, __half* __restrict__ H1,
               __half* __restrict__ H2, float* __restrict__ Y)
{
    extern __shared__ char smem[];
    const uint32_t sb = smem_u32(smem);
    const int t = threadIdx.x;
    const int warp = t >> 5, lane = t & 31;
    const int wm = warp >> 1, wn = warp & 1;
    const int row0 = blockIdx.y * CTA_M;
    const int col0 = blockIdx.x * CTA_N;
    const int z = blockIdx.z;

    const __half* A = (z == 0) ? A0 : (z == 1) ? A1 : A2;
    const __half* B = (z == 0) ? B0 : (z == 1) ? B1 : B2;
    const float* bias = (z == 0) ? bias0 : (z == 1) ? bias1 : bias2;
    __half* H = (z == 0) ? H0 : (z == 1) ? H1 : H2;

    const int lrow = t >> 1;
    const int seg0 = (t & 1) * 2;

    const __half* gA = A + (size_t)(row0 + lrow) * KDIM + seg0 * 8;
    const __half* gB = B + (size_t)(col0 + lrow) * KDIM + seg0 * 8;
    const uint32_t sA0 = sb + lrow * (ASTRIDE * 2) + seg0 * 16;
    const uint32_t sB0 = sA0 + TILE_ELE * 2;

    const int NK = KDIM / CTA_K;   // 32

#pragma unroll
    for (int s = 0; s < STAGES - 1; ++s) {
        const uint32_t so = s * STAGE_ELE * 2;
        cp16(sA0 + so,      gA + s * CTA_K);
        cp16(sA0 + so + 16, gA + s * CTA_K + 8);
        cp16(sB0 + so,      gB + s * CTA_K);
        cp16(sB0 + so + 16, gB + s * CTA_K + 8);
        cp_commit();
    }

    float acc[2][8][4];
#pragma unroll
    for (int i = 0; i < 2; ++i)
#pragma unroll
        for (int j = 0; j < 8; ++j)
#pragma unroll
            for (int c = 0; c < 4; ++c) acc[i][j][c] = 0.f;

    const int g = lane >> 3, r = lane & 7;
    const int aRow = wm * 32 + (g & 1) * 8 + r;
    const int aK   = (g >> 1) * 8;
    const int bRow = wn * 64 + (g >> 1) * 8 + r;
    const int bK   = (g & 1) * 8;

    for (int ks = 0; ks < NK; ++ks) {
        cp_wait<STAGES - 2>();
        __syncthreads();

        const uint32_t so = (ks % STAGES) * STAGE_ELE * 2;
        const uint32_t sAst = sb + so;
        const uint32_t sBst = sAst + TILE_ELE * 2;

#pragma unroll
        for (int kk = 0; kk < 2; ++kk) {
            uint32_t af[2][4], bf[4][4];
#pragma unroll
            for (int mt = 0; mt < 2; ++mt)
                ldsm4(af[mt], sAst + ((aRow + mt * 16) * ASTRIDE + kk * 16 + aK) * 2);
#pragma unroll
            for (int nn = 0; nn < 4; ++nn)
                ldsm4(bf[nn], sBst + ((bRow + nn * 16) * ASTRIDE + kk * 16 + bK) * 2);
#pragma unroll
            for (int mt = 0; mt < 2; ++mt)
#pragma unroll
                for (int nn = 0; nn < 4; ++nn) {
                    mma16816(acc[mt][nn * 2 + 0], af[mt], &bf[nn][0]);
                    mma16816(acc[mt][nn * 2 + 1], af[mt], &bf[nn][2]);
                }
        }

        const int kn = ks + STAGES - 1;
        if (kn < NK) {
            const uint32_t sn = (kn % STAGES) * STAGE_ELE * 2;
            cp16(sA0 + sn,      gA + kn * CTA_K);
            cp16(sA0 + sn + 16, gA + kn * CTA_K + 8);
            cp16(sB0 + sn,      gB + kn * CTA_K);
            cp16(sB0 + sn + 16, gB + kn * CTA_K + 8);
        }
        cp_commit();
        __syncthreads();
    }

    const int mBase = row0 + wm * 32 + (lane >> 2);
    const int nBase = col0 + wn * 64 + (lane & 3) * 2;
#pragma unroll
    for (int mt = 0; mt < 2; ++mt) {
#pragma unroll
        for (int nt = 0; nt < 8; ++nt) {
            const int gcol = nBase + nt * 8;
            const float2 bb = *(const float2*)&bias[gcol];
            const float v0a = acc[mt][nt][0] + bb.x;
            const float v0b = acc[mt][nt][1] + bb.y;
            const float v1a = acc[mt][nt][2] + bb.x;
            const float v1b = acc[mt][nt][3] + bb.y;
            const int grow0 = mBase + mt * 16;
            const int grow1 = grow0 + 8;
            if (HEADS_OUT) {
                const int h = gcol >> 6, c = gcol & 63;
                const int b0 = grow0 >> 11, s0 = grow0 & 2047;
                const int b1 = grow1 >> 11, s1 = grow1 & 2047;
                const size_t d0 = ((size_t)(b0 * 16 + h) * 2048 + s0) * 64 + c;
                const size_t d1 = ((size_t)(b1 * 16 + h) * 2048 + s1) * 64 + c;
                __half2 p0 = __floats2half2_rn(v0a, v0b);
                __half2 p1 = __floats2half2_rn(v1a, v1b);
                *(uint32_t*)(H + d0) = *(uint32_t*)&p0;
                *(uint32_t*)(H + d1) = *(uint32_t*)&p1;
            } else {
                *(float2*)&Y[(size_t)grow0 * DMODEL + gcol] = make_float2(v0a, v0b);
                *(float2*)&Y[(size_t)grow1 * DMODEL + gcol] = make_float2(v1a, v1b);
            }
        }
    }
}

// ---------------------------------------------------------------------------
// Flash attention on fp16 HMMA. Q-tile 128 (4 warps), K-tile 64.
// Single-term QK^T and PV; fp32 accum + online softmax.
// smem (halves): Qs[128][72], Ks[64][72], Vs[64][72]
// ---------------------------------------------------------------------------
#define FS_STR   72
#define SM_Q     0
#define SM_K     (SM_Q + 128 * FS_STR)
#define SM_V     (SM_K + 64 * FS_STR)
#define FLASH_SMEM ((SM_V + 64 * FS_STR) * 2)   // 36864 bytes

__global__ __launch_bounds__(128, 2)
void flash_mma(const __half* __restrict__ Qg, const __half* __restrict__ Kg,
               const __half* __restrict__ Vg, const int* __restrict__ mask,
               __half* __restrict__ Ctx)
{
    extern __shared__ char smem[];
    const uint32_t sb = smem_u32(smem);
    const int t = threadIdx.x;
    const int warp = t >> 5, lane = t & 31;
    const int grp = lane >> 2, tg = lane & 3;
    const int bh = blockIdx.y;
    const int b  = bh >> 4, h = bh & 15;
    const int q0 = blockIdx.x * 128;

    const size_t headOff = (size_t)bh * SEQ * DHEAD;
    const __half* Qhg = Qg + headOff;
    const __half* Khg = Kg + headOff;
    const __half* Vhg = Vg + headOff;

    // load Q tile: 128 rows x 128B = 1024 chunks -> 8/thread
#pragma unroll
    for (int i = 0; i < 8; ++i) {
        const int id = i * 128 + t;
        const int row = id >> 3, seg = id & 7;
        cp16(sb + SM_Q * 2 + row * 144 + seg * 16,
             (const char*)Qhg + (size_t)(q0 + row) * 128 + seg * 16);
    }
    cp_commit();

    const int g2 = lane >> 3, r8 = lane & 7;
    const int arow = (g2 & 1) * 8 + r8;
    const int akoff = (lane >> 4) * 8;
    const int brow = (lane >> 4) * 8 + r8;
    const int bkoff = (g2 & 1) * 8;

    float ctx[2][8][4];
    float mrow[2][2], lrow[2][2];
#pragma unroll
    for (int mt = 0; mt < 2; ++mt) {
        mrow[mt][0] = -INFINITY; mrow[mt][1] = -INFINITY;
        lrow[mt][0] = 0.f; lrow[mt][1] = 0.f;
#pragma unroll
        for (int j = 0; j < 8; ++j)
#pragma unroll
            for (int c = 0; c < 4; ++c) ctx[mt][j][c] = 0.f;
    }

    const int qr0 = q0 + warp * 32 + grp;

    for (int kt = 0; kt < SEQ / 64; ++kt) {
        const int k0 = kt * 64;
        __syncthreads();
        // load K,V: 64 rows x 8 segs = 512 chunks -> 4/thread each
#pragma unroll
        for (int i = 0; i < 4; ++i) {
            const int id = i * 128 + t;
            const int row = id >> 3, seg = id & 7;
            const size_t go = (size_t)(k0 + row) * 128 + seg * 16;
            const uint32_t so = row * 144 + seg * 16;
            cp16(sb + SM_K * 2 + so, (const char*)Khg + go);
            cp16(sb + SM_V * 2 + so, (const char*)Vhg + go);
        }
        cp_commit();
        cp_wait<0>();
        __syncthreads();

        // ---- S = Q K^T ----
        float S[2][8][4];
#pragma unroll
        for (int mt = 0; mt < 2; ++mt)
#pragma unroll
            for (int j = 0; j < 8; ++j)
#pragma unroll
                for (int c = 0; c < 4; ++c) S[mt][j][c] = 0.f;

#pragma unroll
        for (int kk = 0; kk < 4; ++kk) {
            uint32_t aQ[2][4];
#pragma unroll
            for (int mt = 0; mt < 2; ++mt) {
                const uint32_t qa = (warp * 32 + mt * 16 + arow) * FS_STR + kk * 16 + akoff;
                ldsm4(aQ[mt], sb + (SM_Q + qa) * 2);
            }
#pragma unroll
            for (int nt = 0; nt < 4; ++nt) {
                uint32_t bK4[4];
                const uint32_t ka = (nt * 16 + brow) * FS_STR + kk * 16 + bkoff;
                ldsm4(bK4, sb + (SM_K + ka) * 2);
#pragma unroll
                for (int mt = 0; mt < 2; ++mt) {
                    mma16816(S[mt][nt * 2 + 0], aQ[mt], &bK4[0]);
                    mma16816(S[mt][nt * 2 + 1], aQ[mt], &bK4[2]);
                }
            }
        }

        // ---- mask + online softmax + pack P ----
        uint32_t Pf[2][4][4];
#pragma unroll
        for (int mt = 0; mt < 2; ++mt) {
            const int row0 = qr0 + mt * 16;
            const int row1 = row0 + 8;
            float mx0 = -INFINITY, mx1 = -INFINITY;
#pragma unroll
            for (int j = 0; j < 8; ++j) {
                const int kcol = k0 + j * 8 + tg * 2;
                const int2 mv0 = *(const int2*)&mask[(size_t)row0 * SEQ + kcol];
                const int2 mv1 = *(const int2*)&mask[(size_t)row1 * SEQ + kcol];
                S[mt][j][0] = mv0.x ? S[mt][j][0] * 0.125f : -1e9f;
                S[mt][j][1] = mv0.y ? S[mt][j][1] * 0.125f : -1e9f;
                S[mt][j][2] = mv1.x ? S[mt][j][2] * 0.125f : -1e9f;
                S[mt][j][3] = mv1.y ? S[mt][j][3] * 0.125f : -1e9f;
                mx0 = fmaxf(mx0, fmaxf(S[mt][j][0], S[mt][j][1]));
                mx1 = fmaxf(mx1, fmaxf(S[mt][j][2], S[mt][j][3]));
            }
            mx0 = fmaxf(mx0, __shfl_xor_sync(0xffffffffu, mx0, 1));
            mx0 = fmaxf(mx0, __shfl_xor_sync(0xffffffffu, mx0, 2));
            mx1 = fmaxf(mx1, __shfl_xor_sync(0xffffffffu, mx1, 1));
            mx1 = fmaxf(mx1, __shfl_xor_sync(0xffffffffu, mx1, 2));

            const float mn0 = fmaxf(mrow[mt][0], mx0);
            const float mn1 = fmaxf(mrow[mt][1], mx1);
            const float sc0 = __expf(mrow[mt][0] - mn0);
            const float sc1 = __expf(mrow[mt][1] - mn1);
            mrow[mt][0] = mn0; mrow[mt][1] = mn1;

            float sum0 = 0.f, sum1 = 0.f;
#pragma unroll
            for (int j = 0; j < 8; ++j) {
                S[mt][j][0] = __expf(S[mt][j][0] - mn0);
                S[mt][j][1] = __expf(S[mt][j][1] - mn0);
                S[mt][j][2] = __expf(S[mt][j][2] - mn1);
                S[mt][j][3] = __expf(S[mt][j][3] - mn1);
                sum0 += S[mt][j][0] + S[mt][j][1];
                sum1 += S[mt][j][2] + S[mt][j][3];
#pragma unroll
                for (int c = 0; c < 4; ++c)
                    ctx[mt][j][c] *= (c < 2) ? sc0 : sc1;
            }
            sum0 += __shfl_xor_sync(0xffffffffu, sum0, 1);
            sum0 += __shfl_xor_sync(0xffffffffu, sum0, 2);
            sum1 += __shfl_xor_sync(0xffffffffu, sum1, 1);
            sum1 += __shfl_xor_sync(0xffffffffu, sum1, 2);
            lrow[mt][0] = lrow[mt][0] * sc0 + sum0;
            lrow[mt][1] = lrow[mt][1] * sc1 + sum1;

#pragma unroll
            for (int ks = 0; ks < 4; ++ks) {
                Pf[mt][ks][0] = packh2(S[mt][2 * ks][0],     S[mt][2 * ks][1]);
                Pf[mt][ks][1] = packh2(S[mt][2 * ks][2],     S[mt][2 * ks][3]);
                Pf[mt][ks][2] = packh2(S[mt][2 * ks + 1][0], S[mt][2 * ks + 1][1]);
                Pf[mt][ks][3] = packh2(S[mt][2 * ks + 1][2], S[mt][2 * ks + 1][3]);
            }
        }

        // ---- ctx += P V ----
#pragma unroll
        for (int ks = 0; ks < 4; ++ks) {
#pragma unroll
            for (int nt = 0; nt < 4; ++nt) {
                uint32_t vv[4];
                const uint32_t va = (ks * 16 + arow) * FS_STR + nt * 16 + akoff;
                ldsm4t(vv, sb + (SM_V + va) * 2);
#pragma unroll
                for (int mt = 0; mt < 2; ++mt) {
                    mma16816(ctx[mt][nt * 2 + 0], Pf[mt][ks], &vv[0]);
                    mma16816(ctx[mt][nt * 2 + 1], Pf[mt][ks], &vv[2]);
                }
            }
        }
    }

    // ---- epilogue: normalize, write fp16 context row-major [b][s][1024] ----
#pragma unroll
    for (int mt = 0; mt < 2; ++mt) {
        const float inv0 = 1.0f / lrow[mt][0];
        const float inv1 = 1.0f / lrow[mt][1];
        const int row0 = qr0 + mt * 16;
        const int row1 = row0 + 8;
        __half* c0 = Ctx + (size_t)(b * SEQ + row0) * DMODEL + h * DHEAD;
        __half* c1 = Ctx + (size_t)(b * SEQ + row1) * DMODEL + h * DHEAD;
#pragma unroll
        for (int j = 0; j < 8; ++j) {
            const int d = j * 8 + tg * 2;
            __half2 p0 = __floats2half2_rn(ctx[mt][j][0] * inv0, ctx[mt][j][1] * inv0);
            __half2 p1 = __floats2half2_rn(ctx[mt][j][2] * inv1, ctx[mt][j][3] * inv1);
            *(uint32_t*)(c0 + d) = *(uint32_t*)&p0;
            *(uint32_t*)(c1 + d) = *(uint32_t*)&p1;
        }
    }
}

// ---------------------------------------------------------------------------
extern "C" void kernel_launch(void* const* d_in, const int* in_sizes, int n_in,
                              void* d_out, int out_size)
{
    const float* q    = (const float*)d_in[0];
    const float* k    = (const float*)d_in[1];
    const float* v    = (const float*)d_in[2];
    const int*   mask = (const int*)  d_in[3];
    const float* Wq   = (const float*)d_in[4];
    const float* bq   = (const float*)d_in[5];
    const float* Wk   = (const float*)d_in[6];
    const float* bk   = (const float*)d_in[7];
    const float* Wv   = (const float*)d_in[8];
    const float* bv   = (const float*)d_in[9];
    const float* Wo   = (const float*)d_in[10];
    const float* bo   = (const float*)d_in[11];
    float* out = (float*)d_out;

    __half *Xq, *Xk, *Xv, *W0, *W1, *W2, *W3, *Qh, *Kh, *Vh, *Ctx;
    cudaGetSymbolAddress((void**)&Xq, g_Xq);
    cudaGetSymbolAddress((void**)&Xk, g_Xk);
    cudaGetSymbolAddress((void**)&Xv, g_Xv);
    cudaGetSymbolAddress((void**)&W0, g_W0);
    cudaGetSymbolAddress((void**)&W1, g_W1);
    cudaGetSymbolAddress((void**)&W2, g_W2);
    cudaGetSymbolAddress((void**)&W3, g_W3);
    cudaGetSymbolAddress((void**)&Qh, g_Qh);
    cudaGetSymbolAddress((void**)&Kh, g_Kh);
    cudaGetSymbolAddress((void**)&Vh, g_Vh);
    cudaGetSymbolAddress((void**)&Ctx, g_Ctx);

    cudaFuncSetAttribute(gemm_fp16<0>, cudaFuncAttributeMaxDynamicSharedMemorySize, GEMM_SMEM);
    cudaFuncSetAttribute(gemm_fp16<1>, cudaFuncAttributeMaxDynamicSharedMemorySize, GEMM_SMEM);
    cudaFuncSetAttribute(flash_mma, cudaFuncAttributeMaxDynamicSharedMemorySize, FLASH_SMEM);

    const int n4x = MROWS * DMODEL / 4;     // 1,048,576
    const int n4w = DMODEL * DMODEL / 4;    // 262,144

    // converts: inputs (z=3) and all 4 weights (z=4)
    to_half<<<dim3(n4x / 256, 1, 3), 256>>>(q, k, v, nullptr, Xq, Xk, Xv, nullptr, n4x);
    to_half<<<dim3(n4w / 256, 1, 4), 256>>>(Wq, Wk, Wv, Wo, W0, W1, W2, W3, n4w);

    // batched QKV projection -> head-major fp16
    const dim3 qkvGrid(DMODEL / CTA_N, MROWS / CTA_M, 3);   // (8, 32, 3)
    gemm_fp16<1><<<qkvGrid, 256, GEMM_SMEM>>>(Xq, Xk, Xv, W0, W1, W2,
                                              bq, bk, bv, Qh, Kh, Vh, nullptr);

    // attention (fp16 HMMA flash) -> fp16 row-major context
    flash_mma<<<dim3(SEQ / 128, BATCH * NHEAD), 128, FLASH_SMEM>>>(Qh, Kh, Vh, mask, Ctx);

    // output projection (fp32 out)
    const dim3 outGrid(DMODEL / CTA_N, MROWS / CTA_M, 1);
    gemm_fp16<0><<<outGrid, 256, GEMM_SMEM>>>(Ctx, nullptr, nullptr, W3, nullptr, nullptr,
                                              bo, nullptr, nullptr,
                                              nullptr, nullptr, nullptr, out);
}

// round 10
// speedup vs baseline: 6.9010x; 1.2113x over previous
#include <cuda_runtime.h>
#include <cuda_fp16.h>
#include <math.h>
#include <stdint.h>

#define BATCH  2
#define SEQ    2048
#define DMODEL 1024
#define NHEAD  16
#define DHEAD  64
#define MROWS  (BATCH*SEQ)   // 4096
#define KDIM   1024

// ---------------------------------------------------------------------------
// Scratch (__device__ globals; no allocation allowed)
// ---------------------------------------------------------------------------
__device__ __half g_Xq[MROWS*DMODEL];
__device__ __half g_Xk[MROWS*DMODEL];
__device__ __half g_Xv[MROWS*DMODEL];
__device__ __half g_W0[DMODEL*DMODEL];
__device__ __half g_W1[DMODEL*DMODEL];
__device__ __half g_W2[DMODEL*DMODEL];
__device__ __half g_W3[DMODEL*DMODEL];
__device__ __half g_Qh[MROWS*DMODEL];   // head-major [b][h][s][64]
__device__ __half g_Kh[MROWS*DMODEL];
__device__ __half g_Vh[MROWS*DMODEL];
__device__ __half g_Ctx[MROWS*DMODEL];  // row-major fp16 context
__device__ unsigned char g_tileAll[16*32];   // per (qtile128, ktile64) all-nonzero flag

__device__ __forceinline__ uint32_t smem_u32(const void* p) {
    uint32_t a;
    asm("{ .reg .u64 t; cvta.to.shared.u64 t, %1; cvt.u32.u64 %0, t; }" : "=r"(a) : "l"(p));
    return a;
}

// ---------------------------------------------------------------------------
// fp32 -> fp16 convert, batched over blockIdx.z
// ---------------------------------------------------------------------------
__global__ void to_half(const float* __restrict__ s0, const float* __restrict__ s1,
                        const float* __restrict__ s2, const float* __restrict__ s3,
                        __half* __restrict__ d0, __half* __restrict__ d1,
                        __half* __restrict__ d2, __half* __restrict__ d3, int n4)
{
    const int z = blockIdx.z;
    const float* s = (z == 0) ? s0 : (z == 1) ? s1 : (z == 2) ? s2 : s3;
    __half*      d = (z == 0) ? d0 : (z == 1) ? d1 : (z == 2) ? d2 : d3;
    int i = blockIdx.x * blockDim.x + threadIdx.x;
    if (i >= n4) return;
    float4 x = ((const float4*)s)[i];
    __half2 a = __floats2half2_rn(x.x, x.y);
    __half2 b = __floats2half2_rn(x.z, x.w);
    ((uint2*)d)[i] = make_uint2(*(uint32_t*)&a, *(uint32_t*)&b);
}

// ---------------------------------------------------------------------------
// mask tile reduction: flag[qtile][ktile] = all(mask[qtile*128:+128][ktile*64:+64] != 0)
// grid (16,32), 256 threads; each thread ANDs a half-row (32 ints)
// ---------------------------------------------------------------------------
__global__ void mask_tiles(const int* __restrict__ mask, unsigned char* __restrict__ flags)
{
    __shared__ int ok;
    const int t = threadIdx.x;
    if (t == 0) ok = 1;
    __syncthreads();
    const int r  = t >> 1;
    const int c0 = (t & 1) * 32;
    const int* p = mask + (size_t)(blockIdx.x * 128 + r) * SEQ + blockIdx.y * 64 + c0;
    int all = 1;
#pragma unroll
    for (int i = 0; i < 8; ++i) {
        int4 v = ((const int4*)p)[i];
        all &= (v.x != 0) & (v.y != 0) & (v.z != 0) & (v.w != 0);
    }
    if (!all) ok = 0;
    __syncthreads();
    if (t == 0) flags[blockIdx.x * 32 + blockIdx.y] = (unsigned char)ok;
}

// ---------------------------------------------------------------------------
// mma primitives (fp16)
// ---------------------------------------------------------------------------
__device__ __forceinline__ void cp16(uint32_t smem, const void* gmem) {
    asm volatile("cp.async.cg.shared.global [%0], [%1], 16;" :: "r"(smem), "l"(gmem));
}
__device__ __forceinline__ void cp_commit() { asm volatile("cp.async.commit_group;"); }
template<int N> __device__ __forceinline__ void cp_wait() {
    asm volatile("cp.async.wait_group %0;" :: "n"(N));
}
__device__ __forceinline__ void ldsm4(uint32_t* r, uint32_t addr) {
    asm volatile("ldmatrix.sync.aligned.m8n8.x4.shared.b16 {%0,%1,%2,%3}, [%4];"
        : "=r"(r[0]), "=r"(r[1]), "=r"(r[2]), "=r"(r[3]) : "r"(addr));
}
__device__ __forceinline__ void ldsm4t(uint32_t* r, uint32_t addr) {
    asm volatile("ldmatrix.sync.aligned.m8n8.x4.trans.shared.b16 {%0,%1,%2,%3}, [%4];"
        : "=r"(r[0]), "=r"(r[1]), "=r"(r[2]), "=r"(r[3]) : "r"(addr));
}
__device__ __forceinline__ void mma16816(float* d, const uint32_t* a, const uint32_t* b) {
    asm volatile(
        "mma.sync.aligned.m16n8k16.row.col.f32.f16.f16.f32 "
        "{%0,%1,%2,%3}, {%4,%5,%6,%7}, {%8,%9}, {%0,%1,%2,%3};"
        : "+f"(d[0]), "+f"(d[1]), "+f"(d[2]), "+f"(d[3])
        : "r"(a[0]), "r"(a[1]), "r"(a[2]), "r"(a[3]), "r"(b[0]), "r"(b[1]));
}
__device__ __forceinline__ uint32_t packh2(float lo, float hi) {
    uint32_t r;
    asm("cvt.rn.f16x2.f32 %0, %1, %2;" : "=r"(r) : "f"(hi), "f"(lo));
    return r;
}

// ---------------------------------------------------------------------------
// fp16 mma GEMM: Y[M,1024] = A[M,1024] @ B[1024,1024]^T + bias
// CTA 128x128, K-step 32, 4-stage cp.async pipeline, 8 warps.
// ---------------------------------------------------------------------------
#define CTA_M   128
#define CTA_N   128
#define CTA_K   32
#define STAGES  4
#define ASTRIDE 40
#define TILE_ELE  (128 * ASTRIDE)
#define STAGE_ELE (2 * TILE_ELE)
#define GEMM_SMEM (STAGES * STAGE_ELE * 2)

template<int HEADS_OUT>
__global__ __launch_bounds__(256, 2)
void gemm_fp16(const __half* __restrict__ A0, const __half* __restrict__ A1,
               const __half* __restrict__ A2,
               const __half* __restrict__ B0, const __half* __restrict__ B1,
               const __half* __restrict__ B2,
               const float* __restrict__ bias0, const float* __restrict__ bias1,
               const float* __restrict__ bias2,
               __half* __restrict__ H0, __half* __restrict__ H1,
               __half* __restrict__ H2, float* __restrict__ Y)
{
    extern __shared__ char smem[];
    const uint32_t sb = smem_u32(smem);
    const int t = threadIdx.x;
    const int warp = t >> 5, lane = t & 31;
    const int wm = warp >> 1, wn = warp & 1;
    const int row0 = blockIdx.y * CTA_M;
    const int col0 = blockIdx.x * CTA_N;
    const int z = blockIdx.z;

    const __half* A = (z == 0) ? A0 : (z == 1) ? A1 : A2;
    const __half* B = (z == 0) ? B0 : (z == 1) ? B1 : B2;
    const float* bias = (z == 0) ? bias0 : (z == 1) ? bias1 : bias2;
    __half* H = (z == 0) ? H0 : (z == 1) ? H1 : H2;

    const int lrow = t >> 1;
    const int seg0 = (t & 1) * 2;

    const __half* gA = A + (size_t)(row0 + lrow) * KDIM + seg0 * 8;
    const __half* gB = B + (size_t)(col0 + lrow) * KDIM + seg0 * 8;
    const uint32_t sA0 = sb + lrow * (ASTRIDE * 2) + seg0 * 16;
    const uint32_t sB0 = sA0 + TILE_ELE * 2;

    const int NK = KDIM / CTA_K;   // 32

#pragma unroll
    for (int s = 0; s < STAGES - 1; ++s) {
        const uint32_t so = s * STAGE_ELE * 2;
        cp16(sA0 + so,      gA + s * CTA_K);
        cp16(sA0 + so + 16, gA + s * CTA_K + 8);
        cp16(sB0 + so,      gB + s * CTA_K);
        cp16(sB0 + so + 16, gB + s * CTA_K + 8);
        cp_commit();
    }

    float acc[2][8][4];
#pragma unroll
    for (int i = 0; i < 2; ++i)
#pragma unroll
        for (int j = 0; j < 8; ++j)
#pragma unroll
            for (int c = 0; c < 4; ++c) acc[i][j][c] = 0.f;

    const int g = lane >> 3, r = lane & 7;
    const int aRow = wm * 32 + (g & 1) * 8 + r;
    const int aK   = (g >> 1) * 8;
    const int bRow = wn * 64 + (g >> 1) * 8 + r;
    const int bK   = (g & 1) * 8;

    for (int ks = 0; ks < NK; ++ks) {
        cp_wait<STAGES - 2>();
        __syncthreads();

        const uint32_t so = (ks % STAGES) * STAGE_ELE * 2;
        const uint32_t sAst = sb + so;
        const uint32_t sBst = sAst + TILE_ELE * 2;

#pragma unroll
        for (int kk = 0; kk < 2; ++kk) {
            uint32_t af[2][4], bf[4][4];
#pragma unroll
            for (int mt = 0; mt < 2; ++mt)
                ldsm4(af[mt], sAst + ((aRow + mt * 16) * ASTRIDE + kk * 16 + aK) * 2);
#pragma unroll
            for (int nn = 0; nn < 4; ++nn)
                ldsm4(bf[nn], sBst + ((bRow + nn * 16) * ASTRIDE + kk * 16 + bK) * 2);
#pragma unroll
            for (int mt = 0; mt < 2; ++mt)
#pragma unroll
                for (int nn = 0; nn < 4; ++nn) {
                    mma16816(acc[mt][nn * 2 + 0], af[mt], &bf[nn][0]);
                    mma16816(acc[mt][nn * 2 + 1], af[mt], &bf[nn][2]);
                }
        }

        const int kn = ks + STAGES - 1;
        if (kn < NK) {
            const uint32_t sn = (kn % STAGES) * STAGE_ELE * 2;
            cp16(sA0 + sn,      gA + kn * CTA_K);
            cp16(sA0 + sn + 16, gA + kn * CTA_K + 8);
            cp16(sB0 + sn,      gB + kn * CTA_K);
            cp16(sB0 + sn + 16, gB + kn * CTA_K + 8);
        }
        cp_commit();
        __syncthreads();
    }

    const int mBase = row0 + wm * 32 + (lane >> 2);
    const int nBase = col0 + wn * 64 + (lane & 3) * 2;
#pragma unroll
    for (int mt = 0; mt < 2; ++mt) {
#pragma unroll
        for (int nt = 0; nt < 8; ++nt) {
            const int gcol = nBase + nt * 8;
            const float2 bb = *(const float2*)&bias[gcol];
            const float v0a = acc[mt][nt][0] + bb.x;
            const float v0b = acc[mt][nt][1] + bb.y;
            const float v1a = acc[mt][nt][2] + bb.x;
            const float v1b = acc[mt][nt][3] + bb.y;
            const int grow0 = mBase + mt * 16;
            const int grow1 = grow0 + 8;
            if (HEADS_OUT) {
                const int h = gcol >> 6, c = gcol & 63;
                const int b0 = grow0 >> 11, s0 = grow0 & 2047;
                const int b1 = grow1 >> 11, s1 = grow1 & 2047;
                const size_t d0 = ((size_t)(b0 * 16 + h) * 2048 + s0) * 64 + c;
                const size_t d1 = ((size_t)(b1 * 16 + h) * 2048 + s1) * 64 + c;
                __half2 p0 = __floats2half2_rn(v0a, v0b);
                __half2 p1 = __floats2half2_rn(v1a, v1b);
                *(uint32_t*)(H + d0) = *(uint32_t*)&p0;
                *(uint32_t*)(H + d1) = *(uint32_t*)&p1;
            } else {
                *(float2*)&Y[(size_t)grow0 * DMODEL + gcol] = make_float2(v0a, v0b);
                *(float2*)&Y[(size_t)grow1 * DMODEL + gcol] = make_float2(v1a, v1b);
            }
        }
    }
}

// ---------------------------------------------------------------------------
// Flash attention, fp16 HMMA, double-buffered K/V + mask tile flags.
// smem (halves): Q[128][72] + 2 stages of (K[64][72] + V[64][72])
// ---------------------------------------------------------------------------
#define FS_STR   72
#define QELE     (128 * FS_STR)       // 9216
#define KVELE    (64 * FS_STR)        // 4608
#define FLASH_SMEM ((QELE + 4 * KVELE) * 2)   // 55296 bytes

__global__ __launch_bounds__(128, 2)
void flash_mma(const __half* __restrict__ Qg, const __half* __restrict__ Kg,
               const __half* __restrict__ Vg, const int* __restrict__ mask,
               const unsigned char* __restrict__ tileAll, __half* __restrict__ Ctx)
{
    extern __shared__ char smem[];
    const uint32_t sb = smem_u32(smem);
    const int t = threadIdx.x;
    const int warp = t >> 5, lane = t & 31;
    const int grp = lane >> 2, tg = lane & 3;
    const int bh = blockIdx.y;
    const int b  = bh >> 4, h = bh & 15;
    const int q0 = blockIdx.x * 128;

    const size_t headOff = (size_t)bh * SEQ * DHEAD;
    const __half* Qhg = Qg + headOff;
    const __half* Khg = Kg + headOff;
    const __half* Vhg = Vg + headOff;

    const int ldrow = t >> 3, ldseg = t & 7;   // K/V cooperative load mapping

    // prologue: Q + KV(0) as group0; KV(1) as group1
#pragma unroll
    for (int i = 0; i < 8; ++i) {
        const int id = i * 128 + t;
        const int row = id >> 3, seg = id & 7;
        cp16(sb + row * 144 + seg * 16,
             (const char*)Qhg + (size_t)(q0 + row) * 128 + seg * 16);
    }
#pragma unroll
    for (int i = 0; i < 4; ++i) {
        const int row = i * 16 + ldrow;
        const size_t go = (size_t)row * 128 + ldseg * 16;
        const uint32_t so = row * 144 + ldseg * 16;
        cp16(sb + QELE * 2 + so, (const char*)Khg + go);
        cp16(sb + (QELE + KVELE) * 2 + so, (const char*)Vhg + go);
    }
    cp_commit();
#pragma unroll
    for (int i = 0; i < 4; ++i) {
        const int row = i * 16 + ldrow;
        const size_t go = (size_t)(64 + row) * 128 + ldseg * 16;
        const uint32_t so = row * 144 + ldseg * 16;
        cp16(sb + (QELE + 2 * KVELE) * 2 + so, (const char*)Khg + go);
        cp16(sb + (QELE + 3 * KVELE) * 2 + so, (const char*)Vhg + go);
    }
    cp_commit();

    const int g2 = lane >> 3, r8 = lane & 7;
    const int arow = (g2 & 1) * 8 + r8;
    const int akoff = (lane >> 4) * 8;
    const int brow = (lane >> 4) * 8 + r8;
    const int bkoff = (g2 & 1) * 8;

    float ctx[2][8][4];
    float mrow[2][2], lrow[2][2];
#pragma unroll
    for (int mt = 0; mt < 2; ++mt) {
        mrow[mt][0] = -INFINITY; mrow[mt][1] = -INFINITY;
        lrow[mt][0] = 0.f; lrow[mt][1] = 0.f;
#pragma unroll
        for (int j = 0; j < 8; ++j)
#pragma unroll
            for (int c = 0; c < 4; ++c) ctx[mt][j][c] = 0.f;
    }

    const int qr0 = q0 + warp * 32 + grp;
    const unsigned char* flagRow = tileAll + blockIdx.x * 32;

    for (int kt = 0; kt < SEQ / 64; ++kt) {
        const int k0 = kt * 64;
        const int st = kt & 1;
        const uint32_t sK = sb + (QELE + 2 * st * KVELE) * 2;
        const uint32_t sV = sK + KVELE * 2;

        cp_wait<1>();
        __syncthreads();

        const int allOnes = flagRow[kt];

        // ---- S = Q K^T ----
        float S[2][8][4];
#pragma unroll
        for (int mt = 0; mt < 2; ++mt)
#pragma unroll
            for (int j = 0; j < 8; ++j)
#pragma unroll
                for (int c = 0; c < 4; ++c) S[mt][j][c] = 0.f;

#pragma unroll
        for (int kk = 0; kk < 4; ++kk) {
            uint32_t aQ[2][4];
#pragma unroll
            for (int mt = 0; mt < 2; ++mt) {
                const uint32_t qa = (warp * 32 + mt * 16 + arow) * FS_STR + kk * 16 + akoff;
                ldsm4(aQ[mt], sb + qa * 2);
            }
#pragma unroll
            for (int nt = 0; nt < 4; ++nt) {
                uint32_t bK4[4];
                const uint32_t ka = (nt * 16 + brow) * FS_STR + kk * 16 + bkoff;
                ldsm4(bK4, sK + ka * 2);
#pragma unroll
                for (int mt = 0; mt < 2; ++mt) {
                    mma16816(S[mt][nt * 2 + 0], aQ[mt], &bK4[0]);
                    mma16816(S[mt][nt * 2 + 1], aQ[mt], &bK4[2]);
                }
            }
        }

        // ---- mask/scale + online softmax + pack P ----
        uint32_t Pf[2][4][4];
#pragma unroll
        for (int mt = 0; mt < 2; ++mt) {
            const int row0 = qr0 + mt * 16;
            const int row1 = row0 + 8;
            float mx0 = -INFINITY, mx1 = -INFINITY;
            if (allOnes) {
#pragma unroll
                for (int j = 0; j < 8; ++j) {
                    S[mt][j][0] *= 0.125f; S[mt][j][1] *= 0.125f;
                    S[mt][j][2] *= 0.125f; S[mt][j][3] *= 0.125f;
                    mx0 = fmaxf(mx0, fmaxf(S[mt][j][0], S[mt][j][1]));
                    mx1 = fmaxf(mx1, fmaxf(S[mt][j][2], S[mt][j][3]));
                }
            } else {
#pragma unroll
                for (int j = 0; j < 8; ++j) {
                    const int kcol = k0 + j * 8 + tg * 2;
                    const int2 mv0 = *(const int2*)&mask[(size_t)row0 * SEQ + kcol];
                    const int2 mv1 = *(const int2*)&mask[(size_t)row1 * SEQ + kcol];
                    S[mt][j][0] = mv0.x ? S[mt][j][0] * 0.125f : -1e9f;
                    S[mt][j][1] = mv0.y ? S[mt][j][1] * 0.125f : -1e9f;
                    S[mt][j][2] = mv1.x ? S[mt][j][2] * 0.125f : -1e9f;
                    S[mt][j][3] = mv1.y ? S[mt][j][3] * 0.125f : -1e9f;
                    mx0 = fmaxf(mx0, fmaxf(S[mt][j][0], S[mt][j][1]));
                    mx1 = fmaxf(mx1, fmaxf(S[mt][j][2], S[mt][j][3]));
                }
            }
            mx0 = fmaxf(mx0, __shfl_xor_sync(0xffffffffu, mx0, 1));
            mx0 = fmaxf(mx0, __shfl_xor_sync(0xffffffffu, mx0, 2));
            mx1 = fmaxf(mx1, __shfl_xor_sync(0xffffffffu, mx1, 1));
            mx1 = fmaxf(mx1, __shfl_xor_sync(0xffffffffu, mx1, 2));

            const float mn0 = fmaxf(mrow[mt][0], mx0);
            const float mn1 = fmaxf(mrow[mt][1], mx1);
            const float sc0 = __expf(mrow[mt][0] - mn0);
            const float sc1 = __expf(mrow[mt][1] - mn1);
            mrow[mt][0] = mn0; mrow[mt][1] = mn1;

            float sum0 = 0.f, sum1 = 0.f;
#pragma unroll
            for (int j = 0; j < 8; ++j) {
                S[mt][j][0] = __expf(S[mt][j][0] - mn0);
                S[mt][j][1] = __expf(S[mt][j][1] - mn0);
                S[mt][j][2] = __expf(S[mt][j][2] - mn1);
                S[mt][j][3] = __expf(S[mt][j][3] - mn1);
                sum0 += S[mt][j][0] + S[mt][j][1];
                sum1 += S[mt][j][2] + S[mt][j][3];
#pragma unroll
                for (int c = 0; c < 4; ++c)
                    ctx[mt][j][c] *= (c < 2) ? sc0 : sc1;
            }
            sum0 += __shfl_xor_sync(0xffffffffu, sum0, 1);
            sum0 += __shfl_xor_sync(0xffffffffu, sum0, 2);
            sum1 += __shfl_xor_sync(0xffffffffu, sum1, 1);
            sum1 += __shfl_xor_sync(0xffffffffu, sum1, 2);
            lrow[mt][0] = lrow[mt][0] * sc0 + sum0;
            lrow[mt][1] = lrow[mt][1] * sc1 + sum1;

#pragma unroll
            for (int ks = 0; ks < 4; ++ks) {
                Pf[mt][ks][0] = packh2(S[mt][2 * ks][0],     S[mt][2 * ks][1]);
                Pf[mt][ks][1] = packh2(S[mt][2 * ks][2],     S[mt][2 * ks][3]);
                Pf[mt][ks][2] = packh2(S[mt][2 * ks + 1][0], S[mt][2 * ks + 1][1]);
                Pf[mt][ks][3] = packh2(S[mt][2 * ks + 1][2], S[mt][2 * ks + 1][3]);
            }
        }

        // ---- ctx += P V ----
#pragma unroll
        for (int ks = 0; ks < 4; ++ks) {
#pragma unroll
            for (int nt = 0; nt < 4; ++nt) {
                uint32_t vv[4];
                const uint32_t va = (ks * 16 + arow) * FS_STR + nt * 16 + akoff;
                ldsm4t(vv, sV + va * 2);
#pragma unroll
                for (int mt = 0; mt < 2; ++mt) {
                    mma16816(ctx[mt][nt * 2 + 0], Pf[mt][ks], &vv[0]);
                    mma16816(ctx[mt][nt * 2 + 1], Pf[mt][ks], &vv[2]);
                }
            }
        }

        __syncthreads();   // all warps done with stage st before refill

        // prefetch KV(kt+2) into stage st (just freed)
        if (kt + 2 < SEQ / 64) {
            const int kn0 = (kt + 2) * 64;
#pragma unroll
            for (int i = 0; i < 4; ++i) {
                const int row = i * 16 + ldrow;
                const size_t go = (size_t)(kn0 + row) * 128 + ldseg * 16;
                const uint32_t so = row * 144 + ldseg * 16;
                cp16(sK + so, (const char*)Khg + go);
                cp16(sV + so, (const char*)Vhg + go);
            }
        }
        cp_commit();   // always commit (possibly empty group) to keep counts aligned
    }

    // ---- epilogue: normalize, write fp16 context row-major [b][s][1024] ----
#pragma unroll
    for (int mt = 0; mt < 2; ++mt) {
        const float inv0 = 1.0f / lrow[mt][0];
        const float inv1 = 1.0f / lrow[mt][1];
        const int row0 = qr0 + mt * 16;
        const int row1 = row0 + 8;
        __half* c0 = Ctx + (size_t)(b * SEQ + row0) * DMODEL + h * DHEAD;
        __half* c1 = Ctx + (size_t)(b * SEQ + row1) * DMODEL + h * DHEAD;
#pragma unroll
        for (int j = 0; j < 8; ++j) {
            const int d = j * 8 + tg * 2;
            __half2 p0 = __floats2half2_rn(ctx[mt][j][0] * inv0, ctx[mt][j][1] * inv0);
            __half2 p1 = __floats2half2_rn(ctx[mt][j][2] * inv1, ctx[mt][j][3] * inv1);
            *(uint32_t*)(c0 + d) = *(uint32_t*)&p0;
            *(uint32_t*)(c1 + d) = *(uint32_t*)&p1;
        }
    }
}

// ---------------------------------------------------------------------------
extern "C" void kernel_launch(void* const* d_in, const int* in_sizes, int n_in,
                              void* d_out, int out_size)
{
    const float* q    = (const float*)d_in[0];
    const float* k    = (const float*)d_in[1];
    const float* v    = (const float*)d_in[2];
    const int*   mask = (const int*)  d_in[3];
    const float* Wq   = (const float*)d_in[4];
    const float* bq   = (const float*)d_in[5];
    const float* Wk   = (const float*)d_in[6];
    const float* bk   = (const float*)d_in[7];
    const float* Wv   = (const float*)d_in[8];
    const float* bv   = (const float*)d_in[9];
    const float* Wo   = (const float*)d_in[10];
    const float* bo   = (const float*)d_in[11];
    float* out = (float*)d_out;

    __half *Xq, *Xk, *Xv, *W0, *W1, *W2, *W3, *Qh, *Kh, *Vh, *Ctx;
    unsigned char* flags;
    cudaGetSymbolAddress((void**)&Xq, g_Xq);
    cudaGetSymbolAddress((void**)&Xk, g_Xk);
    cudaGetSymbolAddress((void**)&Xv, g_Xv);
    cudaGetSymbolAddress((void**)&W0, g_W0);
    cudaGetSymbolAddress((void**)&W1, g_W1);
    cudaGetSymbolAddress((void**)&W2, g_W2);
    cudaGetSymbolAddress((void**)&W3, g_W3);
    cudaGetSymbolAddress((void**)&Qh, g_Qh);
    cudaGetSymbolAddress((void**)&Kh, g_Kh);
    cudaGetSymbolAddress((void**)&Vh, g_Vh);
    cudaGetSymbolAddress((void**)&Ctx, g_Ctx);
    cudaGetSymbolAddress((void**)&flags, g_tileAll);

    cudaFuncSetAttribute(gemm_fp16<0>, cudaFuncAttributeMaxDynamicSharedMemorySize, GEMM_SMEM);
    cudaFuncSetAttribute(gemm_fp16<1>, cudaFuncAttributeMaxDynamicSharedMemorySize, GEMM_SMEM);
    cudaFuncSetAttribute(flash_mma, cudaFuncAttributeMaxDynamicSharedMemorySize, FLASH_SMEM);

    const int n4x = MROWS * DMODEL / 4;
    const int n4w = DMODEL * DMODEL / 4;

    to_half<<<dim3(n4x / 256, 1, 3), 256>>>(q, k, v, nullptr, Xq, Xk, Xv, nullptr, n4x);
    to_half<<<dim3(n4w / 256, 1, 4), 256>>>(Wq, Wk, Wv, Wo, W0, W1, W2, W3, n4w);
    mask_tiles<<<dim3(16, 32), 256>>>(mask, flags);

    const dim3 qkvGrid(DMODEL / CTA_N, MROWS / CTA_M, 3);
    gemm_fp16<1><<<qkvGrid, 256, GEMM_SMEM>>>(Xq, Xk, Xv, W0, W1, W2,
                                              bq, bk, bv, Qh, Kh, Vh, nullptr);

    flash_mma<<<dim3(SEQ / 128, BATCH * NHEAD), 128, FLASH_SMEM>>>(Qh, Kh, Vh, mask, flags, Ctx);

    const dim3 outGrid(DMODEL / CTA_N, MROWS / CTA_M, 1);
    gemm_fp16<0><<<outGrid, 256, GEMM_SMEM>>>(Ctx, nullptr, nullptr, W3, nullptr, nullptr,
                                              bo, nullptr, nullptr,
                                              nullptr, nullptr, nullptr, out);
}

// round 11
// speedup vs baseline: 7.4138x; 1.0743x over previous
#include <cuda_runtime.h>
#include <cuda_fp16.h>
#include <math.h>
#include <stdint.h>

#define BATCH  2
#define SEQ    2048
#define DMODEL 1024
#define NHEAD  16
#define DHEAD  64
#define MROWS  (BATCH*SEQ)   // 4096
#define KDIM   1024

// ---------------------------------------------------------------------------
// Scratch (__device__ globals; no allocation allowed)
// ---------------------------------------------------------------------------
__device__ __half g_Xq[MROWS*DMODEL];
__device__ __half g_Xk[MROWS*DMODEL];
__device__ __half g_Xv[MROWS*DMODEL];
__device__ __half g_W0[DMODEL*DMODEL];
__device__ __half g_W1[DMODEL*DMODEL];
__device__ __half g_W2[DMODEL*DMODEL];
__device__ __half g_W3[DMODEL*DMODEL];
__device__ __half g_Qh[MROWS*DMODEL];   // head-major [b][h][s][64]
__device__ __half g_Kh[MROWS*DMODEL];
__device__ __half g_Vh[MROWS*DMODEL];
__device__ __half g_Ctx[MROWS*DMODEL];  // row-major fp16 context
__device__ unsigned char g_tileAll[16*32];   // per (qtile128, ktile64) all-nonzero flag

__device__ __forceinline__ uint32_t smem_u32(const void* p) {
    uint32_t a;
    asm("{ .reg .u64 t; cvta.to.shared.u64 t, %1; cvt.u32.u64 %0, t; }" : "=r"(a) : "l"(p));
    return a;
}

// ---------------------------------------------------------------------------
// fp32 -> fp16 convert, 4 float4 per thread (MLP=4), batched over blockIdx.z
// ---------------------------------------------------------------------------
__global__ void to_half(const float* __restrict__ s0, const float* __restrict__ s1,
                        const float* __restrict__ s2, const float* __restrict__ s3,
                        __half* __restrict__ d0, __half* __restrict__ d1,
                        __half* __restrict__ d2, __half* __restrict__ d3, int n4)
{
    const int z = blockIdx.z;
    const float* s = (z == 0) ? s0 : (z == 1) ? s1 : (z == 2) ? s2 : s3;
    __half*      d = (z == 0) ? d0 : (z == 1) ? d1 : (z == 2) ? d2 : d3;
    const int base = blockIdx.x * (blockDim.x * 4) + threadIdx.x;

    float4 x[4];
#pragma unroll
    for (int j = 0; j < 4; ++j) {
        const int idx = base + j * blockDim.x;
        if (idx < n4) x[j] = ((const float4*)s)[idx];
    }
#pragma unroll
    for (int j = 0; j < 4; ++j) {
        const int idx = base + j * blockDim.x;
        if (idx < n4) {
            __half2 a = __floats2half2_rn(x[j].x, x[j].y);
            __half2 b = __floats2half2_rn(x[j].z, x[j].w);
            ((uint2*)d)[idx] = make_uint2(*(uint32_t*)&a, *(uint32_t*)&b);
        }
    }
}

// ---------------------------------------------------------------------------
// mask tile reduction
// ---------------------------------------------------------------------------
__global__ void mask_tiles(const int* __restrict__ mask, unsigned char* __restrict__ flags)
{
    __shared__ int ok;
    const int t = threadIdx.x;
    if (t == 0) ok = 1;
    __syncthreads();
    const int r  = t >> 1;
    const int c0 = (t & 1) * 32;
    const int* p = mask + (size_t)(blockIdx.x * 128 + r) * SEQ + blockIdx.y * 64 + c0;
    int all = 1;
#pragma unroll
    for (int i = 0; i < 8; ++i) {
        int4 v = ((const int4*)p)[i];
        all &= (v.x != 0) & (v.y != 0) & (v.z != 0) & (v.w != 0);
    }
    if (!all) ok = 0;
    __syncthreads();
    if (t == 0) flags[blockIdx.x * 32 + blockIdx.y] = (unsigned char)ok;
}

// ---------------------------------------------------------------------------
// mma primitives (fp16)
// ---------------------------------------------------------------------------
__device__ __forceinline__ void cp16(uint32_t smem, const void* gmem) {
    asm volatile("cp.async.cg.shared.global [%0], [%1], 16;" :: "r"(smem), "l"(gmem));
}
__device__ __forceinline__ void cp_commit() { asm volatile("cp.async.commit_group;"); }
template<int N> __device__ __forceinline__ void cp_wait() {
    asm volatile("cp.async.wait_group %0;" :: "n"(N));
}
__device__ __forceinline__ void ldsm4(uint32_t* r, uint32_t addr) {
    asm volatile("ldmatrix.sync.aligned.m8n8.x4.shared.b16 {%0,%1,%2,%3}, [%4];"
        : "=r"(r[0]), "=r"(r[1]), "=r"(r[2]), "=r"(r[3]) : "r"(addr));
}
__device__ __forceinline__ void ldsm4t(uint32_t* r, uint32_t addr) {
    asm volatile("ldmatrix.sync.aligned.m8n8.x4.trans.shared.b16 {%0,%1,%2,%3}, [%4];"
        : "=r"(r[0]), "=r"(r[1]), "=r"(r[2]), "=r"(r[3]) : "r"(addr));
}
__device__ __forceinline__ void mma16816(float* d, const uint32_t* a, const uint32_t* b) {
    asm volatile(
        "mma.sync.aligned.m16n8k16.row.col.f32.f16.f16.f32 "
        "{%0,%1,%2,%3}, {%4,%5,%6,%7}, {%8,%9}, {%0,%1,%2,%3};"
        : "+f"(d[0]), "+f"(d[1]), "+f"(d[2]), "+f"(d[3])
        : "r"(a[0]), "r"(a[1]), "r"(a[2]), "r"(a[3]), "r"(b[0]), "r"(b[1]));
}
__device__ __forceinline__ uint32_t packh2(float lo, float hi) {
    uint32_t r;
    asm("cvt.rn.f16x2.f32 %0, %1, %2;" : "=r"(r) : "f"(hi), "f"(lo));
    return r;
}

// ---------------------------------------------------------------------------
// fp16 mma GEMM: Y[M,1024] = A[M,1024] @ B[1024,1024]^T + bias
// CTA 128x128, K-step 64 (full 128B rows), 3 stages, 1 barrier/iter,
// prefetch-first ordering. 8 warps, 32x64 warptile.
// ---------------------------------------------------------------------------
#define CTA_M   128
#define CTA_N   128
#define CTA_K   64
#define STAGES  3
#define ASTR    72                          // halves per smem row (144 B)
#define TILE_ELE  (128 * ASTR)              // 9216 halves per operand tile
#define STAGE_ELE (2 * TILE_ELE)
#define GEMM_SMEM (STAGES * STAGE_ELE * 2)  // 110592 bytes

template<int HEADS_OUT>
__global__ __launch_bounds__(256, 2)
void gemm_fp16(const __half* __restrict__ A0, const __half* __restrict__ A1,
               const __half* __restrict__ A2,
               const __half* __restrict__ B0, const __half* __restrict__ B1,
               const __half* __restrict__ B2,
               const float* __restrict__ bias0, const float* __restrict__ bias1,
               const float* __restrict__ bias2,
               __half* __restrict__ H0, __half* __restrict__ H1,
               __half* __restrict__ H2, float* __restrict__ Y)
{
    extern __shared__ char smem[];
    const uint32_t sb = smem_u32(smem);
    const int t = threadIdx.x;
    const int warp = t >> 5, lane = t & 31;
    const int wm = warp >> 1, wn = warp & 1;
    const int row0 = blockIdx.y * CTA_M;
    const int col0 = blockIdx.x * CTA_N;
    const int z = blockIdx.z;

    const __half* A = (z == 0) ? A0 : (z == 1) ? A1 : A2;
    const __half* B = (z == 0) ? B0 : (z == 1) ? B1 : B2;
    const float* bias = (z == 0) ? bias0 : (z == 1) ? bias1 : bias2;
    __half* H = (z == 0) ? H0 : (z == 1) ? H1 : H2;

    // cp.async mapping: per operand per stage = 128 rows x 8 segs (16B).
    // 1024 segs / 256 threads = 4 per thread per operand.
    const int NK = KDIM / CTA_K;   // 16

    // prologue: stages 0,1
#pragma unroll
    for (int s = 0; s < STAGES - 1; ++s) {
        const uint32_t so = sb + s * STAGE_ELE * 2;
#pragma unroll
        for (int i = 0; i < 4; ++i) {
            const int id = i * 256 + t;
            const int row = id >> 3, seg = id & 7;
            const uint32_t sm = row * 144 + seg * 16;
            cp16(so + sm,
                 (const char*)A + ((size_t)(row0 + row) * KDIM + s * CTA_K) * 2 + seg * 16);
            cp16(so + TILE_ELE * 2 + sm,
                 (const char*)B + ((size_t)(col0 + row) * KDIM + s * CTA_K) * 2 + seg * 16);
        }
        cp_commit();
    }

    float acc[2][8][4];
#pragma unroll
    for (int i = 0; i < 2; ++i)
#pragma unroll
        for (int j = 0; j < 8; ++j)
#pragma unroll
            for (int c = 0; c < 4; ++c) acc[i][j][c] = 0.f;

    const int g = lane >> 3, r = lane & 7;
    const int aRow = wm * 32 + (g & 1) * 8 + r;
    const int aK   = (g >> 1) * 8;
    const int bRow = wn * 64 + (g >> 1) * 8 + r;
    const int bK   = (g & 1) * 8;

    for (int ks = 0; ks < NK; ++ks) {
        cp_wait<1>();
        __syncthreads();   // stage ks visible to all; all warps done with stage ks-1

        // prefetch stage ks+2 (into buffer (ks+2)%3 == (ks-1)%3, free by the barrier above)
        const int kn = ks + STAGES - 1;
        if (kn < NK) {
            const uint32_t so = sb + (kn % STAGES) * STAGE_ELE * 2;
#pragma unroll
            for (int i = 0; i < 4; ++i) {
                const int id = i * 256 + t;
                const int row = id >> 3, seg = id & 7;
                const uint32_t sm = row * 144 + seg * 16;
                cp16(so + sm,
                     (const char*)A + ((size_t)(row0 + row) * KDIM + kn * CTA_K) * 2 + seg * 16);
                cp16(so + TILE_ELE * 2 + sm,
                     (const char*)B + ((size_t)(col0 + row) * KDIM + kn * CTA_K) * 2 + seg * 16);
            }
        }
        cp_commit();

        const uint32_t sAst = sb + (ks % STAGES) * STAGE_ELE * 2;
        const uint32_t sBst = sAst + TILE_ELE * 2;

#pragma unroll
        for (int kk = 0; kk < 4; ++kk) {
            uint32_t af[2][4], bf[4][4];
#pragma unroll
            for (int mt = 0; mt < 2; ++mt)
                ldsm4(af[mt], sAst + ((aRow + mt * 16) * ASTR + kk * 16 + aK) * 2);
#pragma unroll
            for (int nn = 0; nn < 4; ++nn)
                ldsm4(bf[nn], sBst + ((bRow + nn * 16) * ASTR + kk * 16 + bK) * 2);
#pragma unroll
            for (int mt = 0; mt < 2; ++mt)
#pragma unroll
                for (int nn = 0; nn < 4; ++nn) {
                    mma16816(acc[mt][nn * 2 + 0], af[mt], &bf[nn][0]);
                    mma16816(acc[mt][nn * 2 + 1], af[mt], &bf[nn][2]);
                }
        }
    }

    const int mBase = row0 + wm * 32 + (lane >> 2);
    const int nBase = col0 + wn * 64 + (lane & 3) * 2;
#pragma unroll
    for (int mt = 0; mt < 2; ++mt) {
#pragma unroll
        for (int nt = 0; nt < 8; ++nt) {
            const int gcol = nBase + nt * 8;
            const float2 bb = *(const float2*)&bias[gcol];
            const float v0a = acc[mt][nt][0] + bb.x;
            const float v0b = acc[mt][nt][1] + bb.y;
            const float v1a = acc[mt][nt][2] + bb.x;
            const float v1b = acc[mt][nt][3] + bb.y;
            const int grow0 = mBase + mt * 16;
            const int grow1 = grow0 + 8;
            if (HEADS_OUT) {
                const int h = gcol >> 6, c = gcol & 63;
                const int b0 = grow0 >> 11, s0 = grow0 & 2047;
                const int b1 = grow1 >> 11, s1 = grow1 & 2047;
                const size_t d0 = ((size_t)(b0 * 16 + h) * 2048 + s0) * 64 + c;
                const size_t d1 = ((size_t)(b1 * 16 + h) * 2048 + s1) * 64 + c;
                __half2 p0 = __floats2half2_rn(v0a, v0b);
                __half2 p1 = __floats2half2_rn(v1a, v1b);
                *(uint32_t*)(H + d0) = *(uint32_t*)&p0;
                *(uint32_t*)(H + d1) = *(uint32_t*)&p1;
            } else {
                *(float2*)&Y[(size_t)grow0 * DMODEL + gcol] = make_float2(v0a, v0b);
                *(float2*)&Y[(size_t)grow1 * DMODEL + gcol] = make_float2(v1a, v1b);
            }
        }
    }
}

// ---------------------------------------------------------------------------
// Flash attention, fp16 HMMA, double-buffered K/V + mask tile flags.
// (unchanged from round 9)
// ---------------------------------------------------------------------------
#define FS_STR   72
#define QELE     (128 * FS_STR)       // 9216
#define KVELE    (64 * FS_STR)        // 4608
#define FLASH_SMEM ((QELE + 4 * KVELE) * 2)   // 55296 bytes

__global__ __launch_bounds__(128, 2)
void flash_mma(const __half* __restrict__ Qg, const __half* __restrict__ Kg,
               const __half* __restrict__ Vg, const int* __restrict__ mask,
               const unsigned char* __restrict__ tileAll, __half* __restrict__ Ctx)
{
    extern __shared__ char smem[];
    const uint32_t sb = smem_u32(smem);
    const int t = threadIdx.x;
    const int warp = t >> 5, lane = t & 31;
    const int grp = lane >> 2, tg = lane & 3;
    const int bh = blockIdx.y;
    const int b  = bh >> 4, h = bh & 15;
    const int q0 = blockIdx.x * 128;

    const size_t headOff = (size_t)bh * SEQ * DHEAD;
    const __half* Qhg = Qg + headOff;
    const __half* Khg = Kg + headOff;
    const __half* Vhg = Vg + headOff;

    const int ldrow = t >> 3, ldseg = t & 7;

    // prologue: Q + KV(0) as group0; KV(1) as group1
#pragma unroll
    for (int i = 0; i < 8; ++i) {
        const int id = i * 128 + t;
        const int row = id >> 3, seg = id & 7;
        cp16(sb + row * 144 + seg * 16,
             (const char*)Qhg + (size_t)(q0 + row) * 128 + seg * 16);
    }
#pragma unroll
    for (int i = 0; i < 4; ++i) {
        const int row = i * 16 + ldrow;
        const size_t go = (size_t)row * 128 + ldseg * 16;
        const uint32_t so = row * 144 + ldseg * 16;
        cp16(sb + QELE * 2 + so, (const char*)Khg + go);
        cp16(sb + (QELE + KVELE) * 2 + so, (const char*)Vhg + go);
    }
    cp_commit();
#pragma unroll
    for (int i = 0; i < 4; ++i) {
        const int row = i * 16 + ldrow;
        const size_t go = (size_t)(64 + row) * 128 + ldseg * 16;
        const uint32_t so = row * 144 + ldseg * 16;
        cp16(sb + (QELE + 2 * KVELE) * 2 + so, (const char*)Khg + go);
        cp16(sb + (QELE + 3 * KVELE) * 2 + so, (const char*)Vhg + go);
    }
    cp_commit();

    const int g2 = lane >> 3, r8 = lane & 7;
    const int arow = (g2 & 1) * 8 + r8;
    const int akoff = (lane >> 4) * 8;
    const int brow = (lane >> 4) * 8 + r8;
    const int bkoff = (g2 & 1) * 8;

    float ctx[2][8][4];
    float mrow[2][2], lrow[2][2];
#pragma unroll
    for (int mt = 0; mt < 2; ++mt) {
        mrow[mt][0] = -INFINITY; mrow[mt][1] = -INFINITY;
        lrow[mt][0] = 0.f; lrow[mt][1] = 0.f;
#pragma unroll
        for (int j = 0; j < 8; ++j)
#pragma unroll
            for (int c = 0; c < 4; ++c) ctx[mt][j][c] = 0.f;
    }

    const int qr0 = q0 + warp * 32 + grp;
    const unsigned char* flagRow = tileAll + blockIdx.x * 32;

    for (int kt = 0; kt < SEQ / 64; ++kt) {
        const int k0 = kt * 64;
        const int st = kt & 1;
        const uint32_t sK = sb + (QELE + 2 * st * KVELE) * 2;
        const uint32_t sV = sK + KVELE * 2;

        cp_wait<1>();
        __syncthreads();

        const int allOnes = flagRow[kt];

        float S[2][8][4];
#pragma unroll
        for (int mt = 0; mt < 2; ++mt)
#pragma unroll
            for (int j = 0; j < 8; ++j)
#pragma unroll
                for (int c = 0; c < 4; ++c) S[mt][j][c] = 0.f;

#pragma unroll
        for (int kk = 0; kk < 4; ++kk) {
            uint32_t aQ[2][4];
#pragma unroll
            for (int mt = 0; mt < 2; ++mt) {
                const uint32_t qa = (warp * 32 + mt * 16 + arow) * FS_STR + kk * 16 + akoff;
                ldsm4(aQ[mt], sb + qa * 2);
            }
#pragma unroll
            for (int nt = 0; nt < 4; ++nt) {
                uint32_t bK4[4];
                const uint32_t ka = (nt * 16 + brow) * FS_STR + kk * 16 + bkoff;
                ldsm4(bK4, sK + ka * 2);
#pragma unroll
                for (int mt = 0; mt < 2; ++mt) {
                    mma16816(S[mt][nt * 2 + 0], aQ[mt], &bK4[0]);
                    mma16816(S[mt][nt * 2 + 1], aQ[mt], &bK4[2]);
                }
            }
        }

        uint32_t Pf[2][4][4];
#pragma unroll
        for (int mt = 0; mt < 2; ++mt) {
            const int row0 = qr0 + mt * 16;
            const int row1 = row0 + 8;
            float mx0 = -INFINITY, mx1 = -INFINITY;
            if (allOnes) {
#pragma unroll
                for (int j = 0; j < 8; ++j) {
                    S[mt][j][0] *= 0.125f; S[mt][j][1] *= 0.125f;
                    S[mt][j][2] *= 0.125f; S[mt][j][3] *= 0.125f;
                    mx0 = fmaxf(mx0, fmaxf(S[mt][j][0], S[mt][j][1]));
                    mx1 = fmaxf(mx1, fmaxf(S[mt][j][2], S[mt][j][3]));
                }
            } else {
#pragma unroll
                for (int j = 0; j < 8; ++j) {
                    const int kcol = k0 + j * 8 + tg * 2;
                    const int2 mv0 = *(const int2*)&mask[(size_t)row0 * SEQ + kcol];
                    const int2 mv1 = *(const int2*)&mask[(size_t)row1 * SEQ + kcol];
                    S[mt][j][0] = mv0.x ? S[mt][j][0] * 0.125f : -1e9f;
                    S[mt][j][1] = mv0.y ? S[mt][j][1] * 0.125f : -1e9f;
                    S[mt][j][2] = mv1.x ? S[mt][j][2] * 0.125f : -1e9f;
                    S[mt][j][3] = mv1.y ? S[mt][j][3] * 0.125f : -1e9f;
                    mx0 = fmaxf(mx0, fmaxf(S[mt][j][0], S[mt][j][1]));
                    mx1 = fmaxf(mx1, fmaxf(S[mt][j][2], S[mt][j][3]));
                }
            }
            mx0 = fmaxf(mx0, __shfl_xor_sync(0xffffffffu, mx0, 1));
            mx0 = fmaxf(mx0, __shfl_xor_sync(0xffffffffu, mx0, 2));
            mx1 = fmaxf(mx1, __shfl_xor_sync(0xffffffffu, mx1, 1));
            mx1 = fmaxf(mx1, __shfl_xor_sync(0xffffffffu, mx1, 2));

            const float mn0 = fmaxf(mrow[mt][0], mx0);
            const float mn1 = fmaxf(mrow[mt][1], mx1);
            const float sc0 = __expf(mrow[mt][0] - mn0);
            const float sc1 = __expf(mrow[mt][1] - mn1);
            mrow[mt][0] = mn0; mrow[mt][1] = mn1;

            float sum0 = 0.f, sum1 = 0.f;
#pragma unroll
            for (int j = 0; j < 8; ++j) {
                S[mt][j][0] = __expf(S[mt][j][0] - mn0);
                S[mt][j][1] = __expf(S[mt][j][1] - mn0);
                S[mt][j][2] = __expf(S[mt][j][2] - mn1);
                S[mt][j][3] = __expf(S[mt][j][3] - mn1);
                sum0 += S[mt][j][0] + S[mt][j][1];
                sum1 += S[mt][j][2] + S[mt][j][3];
#pragma unroll
                for (int c = 0; c < 4; ++c)
                    ctx[mt][j][c] *= (c < 2) ? sc0 : sc1;
            }
            sum0 += __shfl_xor_sync(0xffffffffu, sum0, 1);
            sum0 += __shfl_xor_sync(0xffffffffu, sum0, 2);
            sum1 += __shfl_xor_sync(0xffffffffu, sum1, 1);
            sum1 += __shfl_xor_sync(0xffffffffu, sum1, 2);
            lrow[mt][0] = lrow[mt][0] * sc0 + sum0;
            lrow[mt][1] = lrow[mt][1] * sc1 + sum1;

#pragma unroll
            for (int ks = 0; ks < 4; ++ks) {
                Pf[mt][ks][0] = packh2(S[mt][2 * ks][0],     S[mt][2 * ks][1]);
                Pf[mt][ks][1] = packh2(S[mt][2 * ks][2],     S[mt][2 * ks][3]);
                Pf[mt][ks][2] = packh2(S[mt][2 * ks + 1][0], S[mt][2 * ks + 1][1]);
                Pf[mt][ks][3] = packh2(S[mt][2 * ks + 1][2], S[mt][2 * ks + 1][3]);
            }
        }

#pragma unroll
        for (int ks = 0; ks < 4; ++ks) {
#pragma unroll
            for (int nt = 0; nt < 4; ++nt) {
                uint32_t vv[4];
                const uint32_t va = (ks * 16 + arow) * FS_STR + nt * 16 + akoff;
                ldsm4t(vv, sV + va * 2);
#pragma unroll
                for (int mt = 0; mt < 2; ++mt) {
                    mma16816(ctx[mt][nt * 2 + 0], Pf[mt][ks], &vv[0]);
                    mma16816(ctx[mt][nt * 2 + 1], Pf[mt][ks], &vv[2]);
                }
            }
        }

        __syncthreads();

        if (kt + 2 < SEQ / 64) {
            const int kn0 = (kt + 2) * 64;
#pragma unroll
            for (int i = 0; i < 4; ++i) {
                const int row = i * 16 + ldrow;
                const size_t go = (size_t)(kn0 + row) * 128 + ldseg * 16;
                const uint32_t so = row * 144 + ldseg * 16;
                cp16(sK + so, (const char*)Khg + go);
                cp16(sV + so, (const char*)Vhg + go);
            }
        }
        cp_commit();
    }

#pragma unroll
    for (int mt = 0; mt < 2; ++mt) {
        const float inv0 = 1.0f / lrow[mt][0];
        const float inv1 = 1.0f / lrow[mt][1];
        const int row0 = qr0 + mt * 16;
        const int row1 = row0 + 8;
        __half* c0 = Ctx + (size_t)(b * SEQ + row0) * DMODEL + h * DHEAD;
        __half* c1 = Ctx + (size_t)(b * SEQ + row1) * DMODEL + h * DHEAD;
#pragma unroll
        for (int j = 0; j < 8; ++j) {
            const int d = j * 8 + tg * 2;
            __half2 p0 = __floats2half2_rn(ctx[mt][j][0] * inv0, ctx[mt][j][1] * inv0);
            __half2 p1 = __floats2half2_rn(ctx[mt][j][2] * inv1, ctx[mt][j][3] * inv1);
            *(uint32_t*)(c0 + d) = *(uint32_t*)&p0;
            *(uint32_t*)(c1 + d) = *(uint32_t*)&p1;
        }
    }
}

// ---------------------------------------------------------------------------
extern "C" void kernel_launch(void* const* d_in, const int* in_sizes, int n_in,
                              void* d_out, int out_size)
{
    const float* q    = (const float*)d_in[0];
    const float* k    = (const float*)d_in[1];
    const float* v    = (const float*)d_in[2];
    const int*   mask = (const int*)  d_in[3];
    const float* Wq   = (const float*)d_in[4];
    const float* bq   = (const float*)d_in[5];
    const float* Wk   = (const float*)d_in[6];
    const float* bk   = (const float*)d_in[7];
    const float* Wv   = (const float*)d_in[8];
    const float* bv   = (const float*)d_in[9];
    const float* Wo   = (const float*)d_in[10];
    const float* bo   = (const float*)d_in[11];
    float* out = (float*)d_out;

    __half *Xq, *Xk, *Xv, *W0, *W1, *W2, *W3, *Qh, *Kh, *Vh, *Ctx;
    unsigned char* flags;
    cudaGetSymbolAddress((void**)&Xq, g_Xq);
    cudaGetSymbolAddress((void**)&Xk, g_Xk);
    cudaGetSymbolAddress((void**)&Xv, g_Xv);
    cudaGetSymbolAddress((void**)&W0, g_W0);
    cudaGetSymbolAddress((void**)&W1, g_W1);
    cudaGetSymbolAddress((void**)&W2, g_W2);
    cudaGetSymbolAddress((void**)&W3, g_W3);
    cudaGetSymbolAddress((void**)&Qh, g_Qh);
    cudaGetSymbolAddress((void**)&Kh, g_Kh);
    cudaGetSymbolAddress((void**)&Vh, g_Vh);
    cudaGetSymbolAddress((void**)&Ctx, g_Ctx);
    cudaGetSymbolAddress((void**)&flags, g_tileAll);

    cudaFuncSetAttribute(gemm_fp16<0>, cudaFuncAttributeMaxDynamicSharedMemorySize, GEMM_SMEM);
    cudaFuncSetAttribute(gemm_fp16<1>, cudaFuncAttributeMaxDynamicSharedMemorySize, GEMM_SMEM);
    cudaFuncSetAttribute(flash_mma, cudaFuncAttributeMaxDynamicSharedMemorySize, FLASH_SMEM);

    const int n4x = MROWS * DMODEL / 4;     // 1,048,576
    const int n4w = DMODEL * DMODEL / 4;    // 262,144

    to_half<<<dim3(n4x / 1024, 1, 3), 256>>>(q, k, v, nullptr, Xq, Xk, Xv, nullptr, n4x);
    to_half<<<dim3(n4w / 1024, 1, 4), 256>>>(Wq, Wk, Wv, Wo, W0, W1, W2, W3, n4w);
    mask_tiles<<<dim3(16, 32), 256>>>(mask, flags);

    const dim3 qkvGrid(DMODEL / CTA_N, MROWS / CTA_M, 3);
    gemm_fp16<1><<<qkvGrid, 256, GEMM_SMEM>>>(Xq, Xk, Xv, W0, W1, W2,
                                              bq, bk, bv, Qh, Kh, Vh, nullptr);

    flash_mma<<<dim3(SEQ / 128, BATCH * NHEAD), 128, FLASH_SMEM>>>(Qh, Kh, Vh, mask, flags, Ctx);

    const dim3 outGrid(DMODEL / CTA_N, MROWS / CTA_M, 1);
    gemm_fp16<0><<<outGrid, 256, GEMM_SMEM>>>(Ctx, nullptr, nullptr, W3, nullptr, nullptr,
                                              bo, nullptr, nullptr,
                                              nullptr, nullptr, nullptr, out);
}